// round 15
// baseline (speedup 1.0000x reference)
#include <cuda_runtime.h>
#include <math.h>
#include <stdint.h>

#define NB 32
#define NL 1024
#define NC 512
#define LH 512   // L/2

// ---------------- scratch (device globals; no allocations) ----------------
__device__ float g_res[(size_t)2*NB*NC*NL];
__device__ float g_cv [(size_t)2*NB*NC*86];
__device__ float g_x1 [(size_t)NB*NC*85];
__device__ float g_x1t[(size_t)NB*NC*85];
__device__ float g_xf [(size_t)NB*NC*169];
__device__ float g_xi [(size_t)NB*NC*85];
__device__ float g_xr [(size_t)NB*NC*85];
__device__ float g_yln[(size_t)NB*NC*85];
__device__ float g_y2 [(size_t)NB*NC*1032];
__device__ float g_br [(size_t)NB*NL*2*NC];
__device__ float g_mg [(size_t)NB*NL*NC];
__device__ float g_mgt[(size_t)NB*NL*NC];
__device__ float g_h1 [(size_t)NB*NL*4*NC];
__device__ float g_h2 [(size_t)NB*NL*NC];
__device__ float g_W2a[(size_t)NC*12*NC];
__device__ float g_W2b[(size_t)NC*24*NC];
__device__ float g_Wm [(size_t)2*NC*NC];
__device__ float g_CM0 [85*169];
__device__ float g_CM20[85*85];
__device__ float g_CM1 [43*85];
__device__ float g_CM21[43*43];
__device__ float g_cwT0[(size_t)NC*NC*12];
__device__ float g_cwT1[(size_t)NC*NC*24];
__device__ float g_iwT0[(size_t)NC*NC*85];
__device__ float g_iwT1[(size_t)NC*NC*43];
__device__ float g_f1T [(size_t)NC*4*NC];
__device__ float g_f2T [(size_t)NC*4*NC];
__device__ float g_part[(size_t)16*1024*1024];
__device__ float g_im [(size_t)18*1024*1024];

__device__ __forceinline__ uint32_t f2tf32(float v) {
    uint32_t u;
    asm("cvt.rna.tf32.f32 %0, %1;" : "=r"(u) : "f"(v));
    return u;
}
__device__ __forceinline__ float tfr(float v) { return __uint_as_float(f2tf32(v)); }

__device__ __forceinline__ uint32_t s2u32(const void* p) {
    return (uint32_t)__cvta_generic_to_shared(p);
}
__device__ __forceinline__ void cpa16(uint32_t dst, const void* src) {
    asm volatile("cp.async.cg.shared.global [%0], [%1], 16;" :: "r"(dst), "l"(src));
}
__device__ __forceinline__ void cpa16z(uint32_t dst, const void* src, int srcbytes) {
    asm volatile("cp.async.cg.shared.global [%0], [%1], 16, %2;"
                 :: "r"(dst), "l"(src), "r"(srcbytes));
}
#define CP_COMMIT() asm volatile("cp.async.commit_group;" ::: "memory")
#define CP_WAIT0()  asm volatile("cp.async.wait_group 0;" ::: "memory")

// ---------------- series decomp ----------------
__global__ void decomp_kernel(const float* __restrict__ src, float* __restrict__ res) {
    __shared__ float s[64][33];
    int b = blockIdx.z;
    int c0 = blockIdx.y * 32;
    int l0 = blockIdx.x * 32;
    int tx = threadIdx.x, ty = threadIdx.y;
    for (int r = ty; r < 64; r += 32) {
        int l = l0 - 16 + r;
        l = l < 0 ? 0 : (l > NL - 1 ? NL - 1 : l);
        s[r][tx] = src[((size_t)b*NL + l)*NC + c0 + tx];
    }
    __syncthreads();
    int base = tx + 16;
    float s17 = 0.f;
    #pragma unroll
    for (int j = -8; j <= 8; j++) s17 += s[base + j][ty];
    float s33 = s17;
    #pragma unroll
    for (int j = 9; j <= 16; j++) s33 += s[base - j][ty] + s[base + j][ty];
    float v = s[base][ty];
    size_t o = ((size_t)(b*NC + c0 + ty))*NL + l0 + tx;
    res[o] = v - s17 / 17.0f;
    res[(size_t)NB*NC*NL + o] = v - s33 / 33.0f;
}

// ---------------- fused prep: transposes + DFT mats + tf32 weight copies ----
__global__ void prep_all(const float* __restrict__ mwt, float* __restrict__ Wm,
                         const float* __restrict__ tw0, float* __restrict__ W2a,
                         const float* __restrict__ tw1, float* __restrict__ W2b,
                         float* __restrict__ CM0, float* __restrict__ CM20,
                         float* __restrict__ CM1, float* __restrict__ CM21,
                         const float* __restrict__ cw0, float* __restrict__ cwT0,
                         const float* __restrict__ cw1, float* __restrict__ cwT1,
                         const float* __restrict__ iw0, float* __restrict__ iwT0,
                         const float* __restrict__ iw1, float* __restrict__ iwT1,
                         const float* __restrict__ f1, float* __restrict__ f1T,
                         const float* __restrict__ f2, float* __restrict__ f2T) {
    const double TWO_PI = 6.283185307179586476925286766559;
    const int tM = NC*NC*2, tA = NC*NC*12, tB = NC*NC*24;
    const int c0 = 85*169, c1 = 85*85, c2 = 43*85, c3 = 43*43;
    const int w0 = NC*NC*12, w1 = NC*NC*24, v0 = NC*NC*85, v1 = NC*NC*43;
    const int ff = NC*4*NC;
    long long total = (long long)tM + tA + tB + c0 + c1 + c2 + c3
                    + w0 + w1 + v0 + v1 + ff + ff;
    for (long long idx = (long long)blockIdx.x*blockDim.x + threadIdx.x; idx < total;
         idx += (long long)gridDim.x*blockDim.x) {
        long long i = idx;
        if (i < tM) {
            int o = (int)i / (NC*2);
            int rem = (int)i - o*NC*2;
            int c = rem >> 1, n = rem & 1;
            Wm[((size_t)n*NC + c)*NC + o] = tfr(mwt[i]);
            continue;
        }
        i -= tM;
        if (i < tA) {
            int cin = (int)i / (NC*12);
            int r   = (int)i - cin*(NC*12);
            W2a[(size_t)r*NC + cin] = tfr(tw0[i]);
            continue;
        }
        i -= tA;
        if (i < tB) {
            int cin = (int)i / (NC*24);
            int r   = (int)i - cin*(NC*24);
            W2b[(size_t)r*NC + cin] = tfr(tw1[i]);
            continue;
        }
        i -= tB;
        if (i < c0) {
            int t = (int)i / 169, f = (int)i - t*169;
            CM0[i] = tfr((float)cos(TWO_PI * (double)((long long)f*(t + 84)) / 169.0));
            continue;
        }
        i -= c0;
        if (i < c1) {
            int f = (int)i / 85, t = (int)i - f*85;
            CM20[i] = tfr((float)(cos(TWO_PI * (double)((long long)f*t) / 85.0) / 85.0));
            continue;
        }
        i -= c1;
        if (i < c2) {
            int t = (int)i / 85, f = (int)i - t*85;
            CM1[i] = tfr((float)cos(TWO_PI * (double)((long long)f*(t + 42)) / 85.0));
            continue;
        }
        i -= c2;
        if (i < c3) {
            int f = (int)i / 43, t = (int)i - f*43;
            CM21[i] = tfr((float)(cos(TWO_PI * (double)((long long)f*t) / 43.0) / 43.0));
            continue;
        }
        i -= c3;
        if (i < w0) { cwT0[i] = tfr(cw0[i]); continue; }
        i -= w0;
        if (i < w1) { cwT1[i] = tfr(cw1[i]); continue; }
        i -= w1;
        if (i < v0) { iwT0[i] = tfr(iw0[i]); continue; }
        i -= v0;
        if (i < v1) { iwT1[i] = tfr(iw1[i]); continue; }
        i -= v1;
        if (i < ff) { f1T[i] = tfr(f1[i]); continue; }
        i -= ff;
        f2T[i] = tfr(f2[i]);
    }
}

// ---------------- conv im2col materialization (tf32-rounded output) ---------
template<int KK, int NE2>
__global__ void im2col_conv_k(const float* __restrict__ res, float* __restrict__ out, int pad) {
    int gk = blockIdx.x;
    int cin = gk / KK, t = gk - cin*KK;
    const int N = NB*NE2;
    const float* rbase = res + (size_t)cin*NL;
    float* obase = out + (size_t)gk*N;
    int tb = t - pad;
    for (int gn = threadIdx.x; gn < N; gn += blockDim.x) {
        int b = gn / NE2, q = gn - b*NE2;
        int s = (q >> 1)*KK + tb;
        float v = (s >= 0 && s < LH) ? rbase[(size_t)b*NC*NL + 2*s + (q & 1)] : 0.f;
        obase[gn] = tfr(v);
    }
}

// ---------------- x1: exp-gated interleave (full + rounded copy) -----------
__global__ void x1_kernel(const float* __restrict__ cv, float* __restrict__ x1,
                          float* __restrict__ x1t, int m, int ne2) {
    size_t total = (size_t)NB*NC*m;
    for (size_t idx = (size_t)blockIdx.x*blockDim.x + threadIdx.x; idx < total;
         idx += (size_t)gridDim.x*blockDim.x) {
        int t = (int)(idx % m);
        size_t bc = idx / m;
        const float* c2 = cv + bc*ne2;
        float v = c2[t ^ 1] * expf(c2[t]);
        x1[idx] = v;
        x1t[idx] = tfr(v);
    }
}

// ---------------- GEMM params ----------------
struct GemmP {
    const float* A; int lda;
    const float* Bp; int ldb; long long sBb;
    float* D; long long sDb; int ldd;
    float* D2;
    const float* bias;
    int M, N, K;
    int npos;
    int pad, lhalf, inner;
    int kt, mklen;
    float* part;
};

__device__ __forceinline__ void mma_tf32(float c[4], const uint32_t a[4], const uint32_t b[2]) {
    asm("mma.sync.aligned.m16n8k8.row.col.f32.tf32.tf32.f32 "
        "{%0,%1,%2,%3},{%4,%5,%6,%7},{%8,%9},{%0,%1,%2,%3};"
        : "+f"(c[0]), "+f"(c[1]), "+f"(c[2]), "+f"(c[3])
        : "r"(a[0]), "r"(a[1]), "r"(a[2]), "r"(a[3]), "r"(b[0]), "r"(b[1]));
}

template<int BMODE, int KK>
__device__ __forceinline__ float ldB(const GemmP& p, const float* bbase, int gk) {
    if (gk >= p.K) return 0.f;
    if (BMODE == 0) return bbase[(long long)gk * p.ldb];
    int cin = gk / KK, t = gk - cin*KK;
    return bbase[(long long)cin*p.inner + t];
}

// tf32 mma.sync GEMM, BM=128. BN=64: BK=32 staged; BN=128: BK=16 with cp.async.
// All operands pre-rounded to tf32 by producers (no cvt in mainloop).
// A smem row-major [BM][BK+4]; B smem row-major [BK][BN+8] (conflict-free).
// AASY/BASY: cp.async fills (requires 16B-aligned dense rows).
// RND: 0 none, 1 round output, 2 store D full + D2 rounded.
template<int BN, int BMODE, int KK, int KALIGN, int AASY, int BASY,
         int BIASM, int ACT, int SMODE, int RND, int SPLITK>
__global__ void __launch_bounds__(256, 2)
gemm_k(GemmP p) {
    constexpr int BM = 128;
    constexpr int BK = (BN == 64) ? 32 : 16;
    constexpr int LDA_S = BK + 4, LDB_S = BN + 8;
    constexpr int WR = 4, WC = 2;
    constexpr int WN = BN/WC, NF = WN/8;
    constexpr int AG = BK/8;
    constexpr int ROWSTEP = 1024/BK;
    constexpr int KROWS = 256/BN;       // staged-B k rows per pass
    constexpr int BELEM = BK/KROWS;     // staged-B elems per thread
    constexpr int ASZ = BM*LDA_S, BSZ = BK*LDB_S;
    extern __shared__ float dyn[];
    float* As = dyn;
    float* Bs = dyn + 2*ASZ;

    const int tid = threadIdx.x, lane = tid & 31, warp = tid >> 5;
    const int wr = warp % WR, wc = warp / WR;
    const int m0 = blockIdx.y * BM, n0 = blockIdx.x * BN;

    int kbeg = 0, kend = p.K;
    if (SPLITK > 1) {
        int kc = ((p.K + SPLITK*BK - 1) / (SPLITK*BK)) * BK;
        kbeg = blockIdx.z * kc;
        kend = min(kbeg + kc, p.K);
    }

    // ---- staged A setup ----
    const int ar_ = tid / (BK/4), ak4 = (tid & (BK/4 - 1)) * 4;
    const float* sarow[AG];
    int sastore[AG];
    #pragma unroll
    for (int g = 0; g < AG; g++) {
        sarow[g]   = p.A + (long long)(m0 + ar_ + ROWSTEP*g) * p.lda;
        sastore[g] = (ar_ + ROWSTEP*g)*LDA_S + ak4;
    }
    // ---- staged B setup ----
    const int bnn = tid & (BN - 1);
    const int bkof = tid / BN;
    const float* sbb = p.Bp;
    bool snv = false;
    {
        int gn = n0 + bnn;
        snv = gn < p.N;
        int g = snv ? gn : 0;
        int b = 0, q = g;
        if (!(BMODE == 0 && p.sBb == 0)) { b = g / p.npos; q = g - b*p.npos; }
        sbb = p.Bp + b*p.sBb + q;
    }
    const int c_ = lane & 3, r_ = lane >> 2;
    const int arow_c = wr*32 + r_;

    float acc[2][NF][4];
    #pragma unroll
    for (int mi = 0; mi < 2; mi++)
        #pragma unroll
        for (int ni = 0; ni < NF; ni++)
            #pragma unroll
            for (int e = 0; e < 4; e++) acc[mi][ni][e] = 0.f;

    // ---------------- prologue: fill slab kbeg into buffer 0 ----------------
    if (AASY) {
        #pragma unroll
        for (int g = 0; g < 2; g++) {
            int id = tid + 256*g;
            int row = id >> 2, cc4 = (id & 3) * 4;
            cpa16(s2u32(&As[row*LDA_S + cc4]),
                  p.A + (long long)(m0 + row)*p.lda + kbeg + cc4);
        }
    } else {
        #pragma unroll
        for (int g = 0; g < AG; g++) {
            float rv[4];
            #pragma unroll
            for (int j = 0; j < 4; j++) {
                int gk = kbeg + ak4 + j;
                rv[j] = (KALIGN || gk < p.K) ? sarow[g][gk] : 0.f;
            }
            *(float4*)&As[sastore[g]] = make_float4(rv[0], rv[1], rv[2], rv[3]);
        }
    }
    if (BASY) {
        #pragma unroll
        for (int g = 0; g < 2; g++) {
            int id = tid + 256*g;
            int k = id >> 5, cc4 = (id & 31) * 4;
            int rem = p.N - (n0 + cc4);
            int sb = rem >= 4 ? 16 : (rem > 0 ? rem*4 : 0);
            const float* src = p.Bp + (long long)(kbeg + k)*p.ldb + (sb ? (n0 + cc4) : 0);
            cpa16z(s2u32(&Bs[k*LDB_S + cc4]), src, sb);
        }
    } else {
        #pragma unroll
        for (int r = 0; r < BELEM; r++) {
            int k = bkof + KROWS*r;
            float v = snv ? ldB<BMODE,KK>(p, sbb, kbeg + k) : 0.f;
            Bs[k*LDB_S + bnn] = v;
        }
    }
    if (AASY || BASY) { CP_COMMIT(); CP_WAIT0(); }
    __syncthreads();

    int buf = 0;
    for (int k0 = kbeg; k0 < kend; k0 += BK) {
        int kn = k0 + BK;
        bool more = kn < kend;
        float rsA[AG][4];
        float rsB[BELEM];
        if (more) {
            float* An = As + (buf^1)*ASZ;
            float* Bn = Bs + (buf^1)*BSZ;
            if (AASY) {
                #pragma unroll
                for (int g = 0; g < 2; g++) {
                    int id = tid + 256*g;
                    int row = id >> 2, cc4 = (id & 3) * 4;
                    cpa16(s2u32(&An[row*LDA_S + cc4]),
                          p.A + (long long)(m0 + row)*p.lda + kn + cc4);
                }
            } else {
                #pragma unroll
                for (int g = 0; g < AG; g++)
                    #pragma unroll
                    for (int j = 0; j < 4; j++) {
                        int gk = kn + ak4 + j;
                        rsA[g][j] = (KALIGN || gk < p.K) ? sarow[g][gk] : 0.f;
                    }
            }
            if (BASY) {
                #pragma unroll
                for (int g = 0; g < 2; g++) {
                    int id = tid + 256*g;
                    int k = id >> 5, cc4 = (id & 31) * 4;
                    int rem = p.N - (n0 + cc4);
                    int sb = rem >= 4 ? 16 : (rem > 0 ? rem*4 : 0);
                    const float* src = p.Bp + (long long)(kn + k)*p.ldb + (sb ? (n0 + cc4) : 0);
                    cpa16z(s2u32(&Bn[k*LDB_S + cc4]), src, sb);
                }
            } else {
                #pragma unroll
                for (int r = 0; r < BELEM; r++)
                    rsB[r] = snv ? ldB<BMODE,KK>(p, sbb, kn + bkof + KROWS*r) : 0.f;
            }
            if (AASY || BASY) CP_COMMIT();
        }
        // ---- compute current slab ----
        const float* Ac = As + buf*ASZ;
        const float* Bc = Bs + buf*BSZ;
        #pragma unroll
        for (int kc = 0; kc < BK/8; kc++) {
            uint32_t af[2][4];
            #pragma unroll
            for (int mi = 0; mi < 2; mi++) {
                int rb_ = (arow_c + mi*16)*LDA_S + kc*8 + c_;
                af[mi][0] = __float_as_uint(Ac[rb_]);
                af[mi][1] = __float_as_uint(Ac[rb_ + 8*LDA_S]);
                af[mi][2] = __float_as_uint(Ac[rb_ + 4]);
                af[mi][3] = __float_as_uint(Ac[rb_ + 8*LDA_S + 4]);
            }
            #pragma unroll
            for (int ni = 0; ni < NF; ni++) {
                int nn = wc*WN + ni*8 + r_;
                uint32_t bf[2];
                bf[0] = __float_as_uint(Bc[(kc*8 + c_    )*LDB_S + nn]);
                bf[1] = __float_as_uint(Bc[(kc*8 + c_ + 4)*LDB_S + nn]);
                mma_tf32(acc[0][ni], af[0], bf);
                mma_tf32(acc[1][ni], af[1], bf);
            }
        }
        if (more) {
            float* An = As + (buf^1)*ASZ;
            float* Bn = Bs + (buf^1)*BSZ;
            if (!AASY) {
                #pragma unroll
                for (int g = 0; g < AG; g++)
                    *(float4*)&An[sastore[g]] =
                        make_float4(rsA[g][0], rsA[g][1], rsA[g][2], rsA[g][3]);
            }
            if (!BASY) {
                #pragma unroll
                for (int r = 0; r < BELEM; r++)
                    Bn[(bkof + KROWS*r)*LDB_S + bnn] = rsB[r];
            }
            if (AASY || BASY) CP_WAIT0();
        }
        __syncthreads();
        buf ^= 1;
    }

    // ---- epilogue ----
    if (SPLITK > 1) {
        float* pd = p.part + (size_t)blockIdx.z * ((size_t)p.M * p.N);
        #pragma unroll
        for (int mi = 0; mi < 2; mi++)
            #pragma unroll
            for (int half = 0; half < 2; half++) {
                int row = m0 + wr*32 + mi*16 + r_ + half*8;
                #pragma unroll
                for (int ni = 0; ni < NF; ni++)
                    #pragma unroll
                    for (int e = 0; e < 2; e++) {
                        int gn = n0 + wc*WN + ni*8 + c_*2 + e;
                        if (gn < p.N)
                            pd[(size_t)row*p.N + gn] = acc[mi][ni][half*2 + e];
                    }
            }
        return;
    }
    #pragma unroll
    for (int mi = 0; mi < 2; mi++) {
        #pragma unroll
        for (int half = 0; half < 2; half++) {
            int row = m0 + wr*32 + mi*16 + r_ + half*8;
            float brow = 0.f;
            if (BIASM == 1) brow = p.bias[row];
            else if (BIASM == 3) brow = p.bias[row / p.kt];
            int cout = 0, jj = 0;
            if (SMODE == 1) { cout = row / p.kt; jj = row - cout*p.kt; }
            #pragma unroll
            for (int ni = 0; ni < NF; ni++) {
                #pragma unroll
                for (int e = 0; e < 2; e++) {
                    int gn = n0 + wc*WN + ni*8 + c_*2 + e;
                    if (gn >= p.N) continue;
                    int b, q;
                    if (SMODE == 0 && p.sDb == 0) { b = 0; q = gn; }
                    else { b = gn / p.npos; q = gn - b*p.npos; }
                    float v = acc[mi][ni][half*2 + e] + brow;
                    if (BIASM == 2) v += p.bias[q];
                    if (ACT == 1) v = tanhf(v);
                    else if (ACT == 2) v = fmaxf(v, 0.f);
                    long long addr;
                    if (SMODE == 0) addr = b*p.sDb + (long long)row*p.ldd + q;
                    else addr = b*p.sDb + (long long)cout*p.mklen + (long long)q*p.kt + jj;
                    if (RND == 1) v = tfr(v);
                    p.D[addr] = v;
                    if (RND == 2) p.D2[addr] = tfr(v);
                }
            }
        }
    }
}

// ---------------- split-K reduce + bias + tanh (+optional round) ------------
__global__ void reduce_ep_k(const float* __restrict__ part, float* __restrict__ D,
                            const float* __restrict__ bias,
                            int S, int M, int N, long long sDb, int ldd, int npos, int rnd) {
    int idx = blockIdx.x*blockDim.x + threadIdx.x;
    if (idx >= M*N) return;
    int row = idx / N, gn = idx - row*N;
    size_t st = (size_t)M*N;
    float v = 0.f;
    for (int z = 0; z < S; z++) v += part[(size_t)z*st + idx];
    v = tanhf(v + bias[row]);
    if (rnd) v = tfr(v);
    int b = gn / npos, q = gn - b*npos;
    D[b*sDb + (long long)row*ldd + q] = v;
}

// ---------------- block reduce + layer norms ----------
__device__ __forceinline__ float blk_sum(float v) {
    __shared__ float sb[8];
    #pragma unroll
    for (int o = 16; o; o >>= 1) v += __shfl_xor_sync(0xffffffffu, v, o);
    if ((threadIdx.x & 31) == 0) sb[threadIdx.x >> 5] = v;
    __syncthreads();
    float t = 0.f;
    #pragma unroll
    for (int i = 0; i < 8; i++) t += sb[i];
    __syncthreads();
    return t;
}

__global__ void ln1_kernel(const float* __restrict__ xr, const float* __restrict__ x1,
                           const float* __restrict__ g, const float* __restrict__ bt,
                           float* __restrict__ out, int m) {
    int row = blockIdx.x;
    int b = row / m, t = row - b*m;
    int tid = threadIdx.x;
    size_t base = (size_t)b*NC*m + t;
    float v0 = xr[base + (size_t)tid*m]       + x1[base + (size_t)tid*m];
    float v1 = xr[base + (size_t)(tid+256)*m] + x1[base + (size_t)(tid+256)*m];
    float mu = blk_sum(v0 + v1) * (1.f/NC);
    float d0 = v0 - mu, d1 = v1 - mu;
    float var = blk_sum(d0*d0 + d1*d1) * (1.f/NC);
    float inv = rsqrtf(var + 1e-5f);
    out[base + (size_t)tid*m]       = tfr(d0*inv*g[tid]     + bt[tid]);
    out[base + (size_t)(tid+256)*m] = tfr(d1*inv*g[tid+256] + bt[tid+256]);
}

__global__ void branch_out_kernel(const float* __restrict__ y2, const float* __restrict__ resn,
                                  const float* __restrict__ g, const float* __restrict__ bt,
                                  float* __restrict__ br, int mk, int nbr) {
    int row = blockIdx.x;
    int b = row >> 10, l = row & 1023;
    int li = (l * mk) >> 10;
    int tid = threadIdx.x;
    size_t yb = (size_t)b*NC*mk + li;
    size_t rb = (size_t)b*NC*NL + l;
    float v0 = y2[yb + (size_t)tid*mk]       + resn[rb + (size_t)tid*NL];
    float v1 = y2[yb + (size_t)(tid+256)*mk] + resn[rb + (size_t)(tid+256)*NL];
    float mu = blk_sum(v0 + v1) * (1.f/NC);
    float d0 = v0 - mu, d1 = v1 - mu;
    float var = blk_sum(d0*d0 + d1*d1) * (1.f/NC);
    float inv = rsqrtf(var + 1e-5f);
    float* o = br + (size_t)row*(2*NC) + nbr*NC;
    o[tid]     = tfr(d0*inv*g[tid]     + bt[tid]);
    o[tid+256] = tfr(d1*inv*g[tid+256] + bt[tid+256]);
}

__global__ void final_ln_kernel(const float* __restrict__ mg, const float* __restrict__ h2,
                                const float* __restrict__ g, const float* __restrict__ bt,
                                float* __restrict__ out) {
    int row = blockIdx.x;
    int tid = threadIdx.x;
    size_t base = (size_t)row*NC;
    float v0 = mg[base + tid]       + h2[base + tid];
    float v1 = mg[base + tid + 256] + h2[base + tid + 256];
    float mu = blk_sum(v0 + v1) * (1.f/NC);
    float d0 = v0 - mu, d1 = v1 - mu;
    float var = blk_sum(d0*d0 + d1*d1) * (1.f/NC);
    float inv = rsqrtf(var + 1e-5f);
    out[base + tid]       = d0*inv*g[tid]     + bt[tid];
    out[base + tid + 256] = d1*inv*g[tid+256] + bt[tid+256];
}

template<int BN, int SPLITK>
static inline dim3 gg(int M, int N) { return dim3((N + BN - 1)/BN, M/128, SPLITK); }

template<int BN, int BMODE, int KK, int KALIGN, int AASY, int BASY,
         int BIASM, int ACT, int SMODE, int RND, int SPLITK = 1>
static void launch_gemm(const GemmP& p) {
    constexpr int BK = (BN == 64) ? 32 : 16;
    constexpr int SMEM = 2*(128*(BK + 4) + BK*(BN + 8))*4;
    cudaFuncSetAttribute((const void*)gemm_k<BN,BMODE,KK,KALIGN,AASY,BASY,BIASM,ACT,SMODE,RND,SPLITK>,
                         cudaFuncAttributeMaxDynamicSharedMemorySize, SMEM);
    gemm_k<BN,BMODE,KK,KALIGN,AASY,BASY,BIASM,ACT,SMODE,RND,SPLITK>
        <<<gg<BN,SPLITK>(p.M, p.N), 256, SMEM>>>(p);
}

extern "C" void kernel_launch(void* const* d_in, const int* in_sizes, int n_in,
                              void* d_out, int out_size) {
    (void)in_sizes; (void)n_in; (void)out_size;
    const float* src   = (const float*)d_in[0];
    const float* cw[2] = {(const float*)d_in[1],  (const float*)d_in[7]};
    const float* cb[2] = {(const float*)d_in[2],  (const float*)d_in[8]};
    const float* iw[2] = {(const float*)d_in[3],  (const float*)d_in[9]};
    const float* ib[2] = {(const float*)d_in[4],  (const float*)d_in[10]};
    const float* tw[2] = {(const float*)d_in[5],  (const float*)d_in[11]};
    const float* tb[2] = {(const float*)d_in[6],  (const float*)d_in[12]};
    const float* mw  = (const float*)d_in[13];
    const float* mb  = (const float*)d_in[14];
    const float* ng  = (const float*)d_in[15];
    const float* nb  = (const float*)d_in[16];
    const float* fw1 = (const float*)d_in[17];
    const float* fb1 = (const float*)d_in[18];
    const float* fw2 = (const float*)d_in[19];
    const float* fb2 = (const float*)d_in[20];
    const float* fng = (const float*)d_in[21];
    const float* fnb = (const float*)d_in[22];
    float* out = (float*)d_out;

    float *p_res,*p_cv,*p_x1,*p_x1t,*p_xf,*p_xi,*p_xr,*p_yln,*p_y2,*p_br,*p_mg,*p_mgt,*p_h1,*p_h2;
    float *p_W2a,*p_W2b,*p_Wm,*p_CM0,*p_CM20,*p_CM1,*p_CM21,*p_part,*p_im;
    float *p_cwT0,*p_cwT1,*p_iwT0,*p_iwT1,*p_f1T,*p_f2T;
    cudaGetSymbolAddress((void**)&p_res, g_res);
    cudaGetSymbolAddress((void**)&p_cv,  g_cv);
    cudaGetSymbolAddress((void**)&p_x1,  g_x1);
    cudaGetSymbolAddress((void**)&p_x1t, g_x1t);
    cudaGetSymbolAddress((void**)&p_xf,  g_xf);
    cudaGetSymbolAddress((void**)&p_xi,  g_xi);
    cudaGetSymbolAddress((void**)&p_xr,  g_xr);
    cudaGetSymbolAddress((void**)&p_yln, g_yln);
    cudaGetSymbolAddress((void**)&p_y2,  g_y2);
    cudaGetSymbolAddress((void**)&p_br,  g_br);
    cudaGetSymbolAddress((void**)&p_mg,  g_mg);
    cudaGetSymbolAddress((void**)&p_mgt, g_mgt);
    cudaGetSymbolAddress((void**)&p_h1,  g_h1);
    cudaGetSymbolAddress((void**)&p_h2,  g_h2);
    cudaGetSymbolAddress((void**)&p_W2a, g_W2a);
    cudaGetSymbolAddress((void**)&p_W2b, g_W2b);
    cudaGetSymbolAddress((void**)&p_Wm,  g_Wm);
    cudaGetSymbolAddress((void**)&p_CM0, g_CM0);
    cudaGetSymbolAddress((void**)&p_CM20,g_CM20);
    cudaGetSymbolAddress((void**)&p_CM1, g_CM1);
    cudaGetSymbolAddress((void**)&p_CM21,g_CM21);
    cudaGetSymbolAddress((void**)&p_part,g_part);
    cudaGetSymbolAddress((void**)&p_im,  g_im);
    cudaGetSymbolAddress((void**)&p_cwT0,g_cwT0);
    cudaGetSymbolAddress((void**)&p_cwT1,g_cwT1);
    cudaGetSymbolAddress((void**)&p_iwT0,g_iwT0);
    cudaGetSymbolAddress((void**)&p_iwT1,g_iwT1);
    cudaGetSymbolAddress((void**)&p_f1T, g_f1T);
    cudaGetSymbolAddress((void**)&p_f2T, g_f2T);

    const int Kk[2] = {12, 24}, NE[2] = {43, 22},
              MM[2] = {85, 43}, N2_[2] = {169, 85}, MKl[2] = {1020, 1032};
    float* CMv[2]  = {p_CM0, p_CM1};
    float* CM2v[2] = {p_CM20, p_CM21};
    float* W2v[2]  = {p_W2a, p_W2b};
    float* cwTv[2] = {p_cwT0, p_cwT1};
    float* iwTv[2] = {p_iwT0, p_iwT1};

    decomp_kernel<<<dim3(NL/32, NC/32, NB), dim3(32, 32)>>>(src, p_res);
    prep_all<<<4096, 256>>>(mw, p_Wm, tw[0], p_W2a, tw[1], p_W2b,
                            p_CM0, p_CM20, p_CM1, p_CM21,
                            cw[0], p_cwT0, cw[1], p_cwT1,
                            iw[0], p_iwT0, iw[1], p_iwT1,
                            fw1, p_f1T, fw2, p_f2T);

    // conv via materialized im2col + dense split-K GEMM (async both operands)
    for (int n = 0; n < 2; n++) {
        int k = Kk[n], ne2 = 2*NE[n];
        int Nn = NB*ne2;
        if (n == 0) im2col_conv_k<12,86><<<NC*12, 256>>>(p_res, p_im, 6);
        else        im2col_conv_k<24,44><<<NC*24, 256>>>(p_res + (size_t)NB*NC*NL, p_im, 12);
        GemmP p{};
        p.A = cwTv[n]; p.lda = NC*k;
        p.Bp = p_im; p.ldb = Nn; p.sBb = 0;
        p.part = p_part;
        p.bias = cb[n];
        p.M = NC; p.N = Nn; p.K = NC*k; p.npos = ne2;
        if (n == 0) launch_gemm<128,0,1,1,1,1,1,1,0,0,10>(p);
        else        launch_gemm<128,0,1,1,1,1,1,1,0,0,20>(p);
        reduce_ep_k<<<(NC*Nn + 255)/256, 256>>>(p_part, p_cv + (size_t)n*NB*NC*86, cb[n],
                                                (n == 0) ? 10 : 20, NC, Nn,
                                                (long long)NC*ne2, ne2, ne2, 0);
    }

    for (int n = 0; n < 2; n++) {
        int k = Kk[n], m = MM[n], N2 = N2_[n], mk = MKl[n];
        int ne2 = 2*NE[n];

        x1_kernel<<<1024, 256>>>(p_cv + (size_t)n*NB*NC*86, p_x1, p_x1t, m, ne2);
        { // real-DFT (ragged K, staged both; output rounded for iso B)
            GemmP p{};
            p.A = p_x1t; p.lda = m;
            p.Bp = CMv[n]; p.ldb = N2; p.sBb = 0;
            p.D = p_xf; p.sDb = 0; p.ldd = N2;
            p.M = NB*NC; p.N = N2; p.K = m; p.npos = N2;
            launch_gemm<64,0,1,0,0,0,0,0,0,1,1>(p);
        }
        { // isometric conv (valid), tanh — split-K, async A, staged B
            GemmP p{};
            p.A = iwTv[n]; p.lda = NC*m;
            p.Bp = p_xf; p.sBb = (long long)NC*N2; p.inner = N2;
            p.part = p_part;
            p.bias = ib[n];
            p.M = NC; p.N = NB*m; p.K = NC*m; p.npos = m;
            if (n == 0) launch_gemm<128,2,85,1,1,0,1,1,0,0,10>(p);
            else        launch_gemm<128,2,43,1,1,0,1,1,0,0,20>(p);
            reduce_ep_k<<<(NC*NB*m + 255)/256, 256>>>(p_part, p_xi, ib[n],
                                                      (n == 0) ? 10 : 20, NC, NB*m,
                                                      (long long)NC*m, m, m, 1);
        }
        { // real-IDFT (ragged K, staged both; xr full for residual)
            GemmP p{};
            p.A = p_xi; p.lda = m;
            p.Bp = CM2v[n]; p.ldb = m; p.sBb = 0;
            p.D = p_xr; p.sDb = 0; p.ldd = m;
            p.M = NB*NC; p.N = m; p.K = m; p.npos = m;
            launch_gemm<64,0,1,0,0,0,0,0,0,0,1>(p);
        }
        ln1_kernel<<<NB*m, 256>>>(p_xr, p_x1, ng, nb, p_yln, m);
        { // conv-transpose, tanh, scatter store — async A, staged B (ldb=85)
            GemmP p{};
            p.A = W2v[n]; p.lda = NC;
            p.Bp = p_yln; p.ldb = m; p.sBb = (long long)NC*m;
            p.D = p_y2; p.sDb = (long long)NC*mk; p.kt = k; p.mklen = mk;
            p.bias = tb[n];
            p.M = NC*k; p.N = NB*m; p.K = NC; p.npos = m;
            launch_gemm<128,0,1,1,1,0,3,1,1,0,1>(p);
        }
        branch_out_kernel<<<NB*NL, 256>>>(p_y2, p_res + (size_t)n*NB*NC*NL, ng, nb, p_br, mk, n);
    }
    { // merge — async both; dual store (mg full + mgt rounded)
        GemmP p{};
        p.A = p_br; p.lda = 2*NC;
        p.Bp = p_Wm; p.ldb = NC; p.sBb = 0;
        p.D = p_mg; p.D2 = p_mgt; p.sDb = 0; p.ldd = NC;
        p.bias = mb;
        p.M = NB*NL; p.N = NC; p.K = 2*NC; p.npos = NC;
        launch_gemm<128,0,1,1,1,1,2,0,0,2,1>(p);
    }
    { // FFN layer 1 (relu) — async both; h1 rounded
        GemmP p{};
        p.A = p_mgt; p.lda = NC;
        p.Bp = p_f1T; p.ldb = 4*NC; p.sBb = 0;
        p.D = p_h1; p.sDb = 0; p.ldd = 4*NC;
        p.bias = fb1;
        p.M = NB*NL; p.N = 4*NC; p.K = NC; p.npos = 4*NC;
        launch_gemm<128,0,1,1,1,1,2,2,0,1,1>(p);
    }
    { // FFN layer 2 — async both
        GemmP p{};
        p.A = p_h1; p.lda = 4*NC;
        p.Bp = p_f2T; p.ldb = NC; p.sBb = 0;
        p.D = p_h2; p.sDb = 0; p.ldd = NC;
        p.bias = fb2;
        p.M = NB*NL; p.N = NC; p.K = 4*NC; p.npos = NC;
        launch_gemm<128,0,1,1,1,1,2,0,0,0,1>(p);
    }
    final_ln_kernel<<<NB*NL, 256>>>(p_mg, p_h2, fng, fnb, out);
}

// round 16
// speedup vs baseline: 1.0481x; 1.0481x over previous
#include <cuda_runtime.h>
#include <math.h>
#include <stdint.h>

#define NB 32
#define NL 1024
#define NC 512
#define LH 512   // L/2

// ---------------- scratch (device globals; no allocations) ----------------
__device__ float g_res[(size_t)2*NB*NC*NL];
__device__ float g_cv [(size_t)2*NB*NC*86];
__device__ float g_x1 [(size_t)NB*NC*85];
__device__ float g_x1t[(size_t)NB*NC*85];
__device__ float g_xf [(size_t)NB*NC*169];
__device__ float g_xi [(size_t)NB*NC*85];
__device__ float g_xr [(size_t)NB*NC*85];
__device__ float g_yln[(size_t)NB*NC*85];
__device__ float g_y2 [(size_t)NB*NC*1032];
__device__ float g_br [(size_t)NB*NL*2*NC];
__device__ float g_mg [(size_t)NB*NL*NC];
__device__ float g_mgt[(size_t)NB*NL*NC];
__device__ float g_h1 [(size_t)NB*NL*4*NC];
__device__ float g_h2 [(size_t)NB*NL*NC];
__device__ float g_W2a[(size_t)NC*12*NC];
__device__ float g_W2b[(size_t)NC*24*NC];
__device__ float g_Wm [(size_t)2*NC*NC];
__device__ float g_CM0 [85*169];
__device__ float g_CM20[85*85];
__device__ float g_CM1 [43*85];
__device__ float g_CM21[43*43];
__device__ float g_cwT0[(size_t)NC*NC*12];
__device__ float g_cwT1[(size_t)NC*NC*24];
__device__ float g_iwT0[(size_t)NC*NC*85];
__device__ float g_iwT1[(size_t)NC*NC*43];
__device__ float g_f1T [(size_t)NC*4*NC];
__device__ float g_f2T [(size_t)NC*4*NC];
__device__ float g_part[(size_t)16*1024*1024];
__device__ float g_im [(size_t)18*1024*1024];

__device__ __forceinline__ uint32_t f2tf32(float v) {
    uint32_t u;
    asm("cvt.rna.tf32.f32 %0, %1;" : "=r"(u) : "f"(v));
    return u;
}
__device__ __forceinline__ float tfr(float v) { return __uint_as_float(f2tf32(v)); }

__device__ __forceinline__ uint32_t s2u32(const void* p) {
    return (uint32_t)__cvta_generic_to_shared(p);
}
__device__ __forceinline__ void cpa16(uint32_t dst, const void* src) {
    asm volatile("cp.async.cg.shared.global [%0], [%1], 16;" :: "r"(dst), "l"(src));
}
__device__ __forceinline__ void cpa16z(uint32_t dst, const void* src, int srcbytes) {
    asm volatile("cp.async.cg.shared.global [%0], [%1], 16, %2;"
                 :: "r"(dst), "l"(src), "r"(srcbytes));
}
#define CP_COMMIT() asm volatile("cp.async.commit_group;" ::: "memory")
#define CP_WAIT0()  asm volatile("cp.async.wait_group 0;" ::: "memory")
#define CP_WAIT1()  asm volatile("cp.async.wait_group 1;" ::: "memory")

// ---------------- series decomp ----------------
__global__ void decomp_kernel(const float* __restrict__ src, float* __restrict__ res) {
    __shared__ float s[64][33];
    int b = blockIdx.z;
    int c0 = blockIdx.y * 32;
    int l0 = blockIdx.x * 32;
    int tx = threadIdx.x, ty = threadIdx.y;
    for (int r = ty; r < 64; r += 32) {
        int l = l0 - 16 + r;
        l = l < 0 ? 0 : (l > NL - 1 ? NL - 1 : l);
        s[r][tx] = src[((size_t)b*NL + l)*NC + c0 + tx];
    }
    __syncthreads();
    int base = tx + 16;
    float s17 = 0.f;
    #pragma unroll
    for (int j = -8; j <= 8; j++) s17 += s[base + j][ty];
    float s33 = s17;
    #pragma unroll
    for (int j = 9; j <= 16; j++) s33 += s[base - j][ty] + s[base + j][ty];
    float v = s[base][ty];
    size_t o = ((size_t)(b*NC + c0 + ty))*NL + l0 + tx;
    res[o] = v - s17 / 17.0f;
    res[(size_t)NB*NC*NL + o] = v - s33 / 33.0f;
}

// ---------------- fused prep ----------------
__global__ void prep_all(const float* __restrict__ mwt, float* __restrict__ Wm,
                         const float* __restrict__ tw0, float* __restrict__ W2a,
                         const float* __restrict__ tw1, float* __restrict__ W2b,
                         float* __restrict__ CM0, float* __restrict__ CM20,
                         float* __restrict__ CM1, float* __restrict__ CM21,
                         const float* __restrict__ cw0, float* __restrict__ cwT0,
                         const float* __restrict__ cw1, float* __restrict__ cwT1,
                         const float* __restrict__ iw0, float* __restrict__ iwT0,
                         const float* __restrict__ iw1, float* __restrict__ iwT1,
                         const float* __restrict__ f1, float* __restrict__ f1T,
                         const float* __restrict__ f2, float* __restrict__ f2T) {
    const double TWO_PI = 6.283185307179586476925286766559;
    const int tM = NC*NC*2, tA = NC*NC*12, tB = NC*NC*24;
    const int c0 = 85*169, c1 = 85*85, c2 = 43*85, c3 = 43*43;
    const int w0 = NC*NC*12, w1 = NC*NC*24, v0 = NC*NC*85, v1 = NC*NC*43;
    const int ff = NC*4*NC;
    long long total = (long long)tM + tA + tB + c0 + c1 + c2 + c3
                    + w0 + w1 + v0 + v1 + ff + ff;
    for (long long idx = (long long)blockIdx.x*blockDim.x + threadIdx.x; idx < total;
         idx += (long long)gridDim.x*blockDim.x) {
        long long i = idx;
        if (i < tM) {
            int o = (int)i / (NC*2);
            int rem = (int)i - o*NC*2;
            int c = rem >> 1, n = rem & 1;
            Wm[((size_t)n*NC + c)*NC + o] = tfr(mwt[i]);
            continue;
        }
        i -= tM;
        if (i < tA) {
            int cin = (int)i / (NC*12);
            int r   = (int)i - cin*(NC*12);
            W2a[(size_t)r*NC + cin] = tfr(tw0[i]);
            continue;
        }
        i -= tA;
        if (i < tB) {
            int cin = (int)i / (NC*24);
            int r   = (int)i - cin*(NC*24);
            W2b[(size_t)r*NC + cin] = tfr(tw1[i]);
            continue;
        }
        i -= tB;
        if (i < c0) {
            int t = (int)i / 169, f = (int)i - t*169;
            CM0[i] = tfr((float)cos(TWO_PI * (double)((long long)f*(t + 84)) / 169.0));
            continue;
        }
        i -= c0;
        if (i < c1) {
            int f = (int)i / 85, t = (int)i - f*85;
            CM20[i] = tfr((float)(cos(TWO_PI * (double)((long long)f*t) / 85.0) / 85.0));
            continue;
        }
        i -= c1;
        if (i < c2) {
            int t = (int)i / 85, f = (int)i - t*85;
            CM1[i] = tfr((float)cos(TWO_PI * (double)((long long)f*(t + 42)) / 85.0));
            continue;
        }
        i -= c2;
        if (i < c3) {
            int f = (int)i / 43, t = (int)i - f*43;
            CM21[i] = tfr((float)(cos(TWO_PI * (double)((long long)f*t) / 43.0) / 43.0));
            continue;
        }
        i -= c3;
        if (i < w0) { cwT0[i] = tfr(cw0[i]); continue; }
        i -= w0;
        if (i < w1) { cwT1[i] = tfr(cw1[i]); continue; }
        i -= w1;
        if (i < v0) { iwT0[i] = tfr(iw0[i]); continue; }
        i -= v0;
        if (i < v1) { iwT1[i] = tfr(iw1[i]); continue; }
        i -= v1;
        if (i < ff) { f1T[i] = tfr(f1[i]); continue; }
        i -= ff;
        f2T[i] = tfr(f2[i]);
    }
}

// ---------------- conv im2col materialization (tf32-rounded output) ---------
template<int KK, int NE2>
__global__ void im2col_conv_k(const float* __restrict__ res, float* __restrict__ out, int pad) {
    int gk = blockIdx.x;
    int cin = gk / KK, t = gk - cin*KK;
    const int N = NB*NE2;
    const float* rbase = res + (size_t)cin*NL;
    float* obase = out + (size_t)gk*N;
    int tb = t - pad;
    for (int gn = threadIdx.x; gn < N; gn += blockDim.x) {
        int b = gn / NE2, q = gn - b*NE2;
        int s = (q >> 1)*KK + tb;
        float v = (s >= 0 && s < LH) ? rbase[(size_t)b*NC*NL + 2*s + (q & 1)] : 0.f;
        obase[gn] = tfr(v);
    }
}

// ---------------- x1: exp-gated interleave (full + rounded copy) -----------
__global__ void x1_kernel(const float* __restrict__ cv, float* __restrict__ x1,
                          float* __restrict__ x1t, int m, int ne2) {
    size_t total = (size_t)NB*NC*m;
    for (size_t idx = (size_t)blockIdx.x*blockDim.x + threadIdx.x; idx < total;
         idx += (size_t)gridDim.x*blockDim.x) {
        int t = (int)(idx % m);
        size_t bc = idx / m;
        const float* c2 = cv + bc*ne2;
        float v = c2[t ^ 1] * expf(c2[t]);
        x1[idx] = v;
        x1t[idx] = tfr(v);
    }
}

// ---------------- GEMM params ----------------
struct GemmP {
    const float* A; int lda;
    const float* Bp; int ldb; long long sBb;
    float* D; long long sDb; int ldd;
    float* D2;
    const float* bias;
    int M, N, K;
    int npos;
    int pad, lhalf, inner;
    int kt, mklen;
    float* part;
};

__device__ __forceinline__ void mma_tf32(float c[4], const uint32_t a[4], const uint32_t b[2]) {
    asm("mma.sync.aligned.m16n8k8.row.col.f32.tf32.tf32.f32 "
        "{%0,%1,%2,%3},{%4,%5,%6,%7},{%8,%9},{%0,%1,%2,%3};"
        : "+f"(c[0]), "+f"(c[1]), "+f"(c[2]), "+f"(c[3])
        : "r"(a[0]), "r"(a[1]), "r"(a[2]), "r"(a[3]), "r"(b[0]), "r"(b[1]));
}

template<int BMODE, int KK>
__device__ __forceinline__ float ldB(const GemmP& p, const float* bbase, int gk) {
    if (gk >= p.K) return 0.f;
    if (BMODE == 0) return bbase[(long long)gk * p.ldb];
    int cin = gk / KK, t = gk - cin*KK;
    return bbase[(long long)cin*p.inner + t];
}

// tf32 mma.sync GEMM, BM=128. BN=64: BK=32 staged; BN=128: BK=16.
// AASY&&BASY: 3-stage cp.async ring (2-slab latency tolerance).
// Other configs: double-buffered (register-staged where not async).
// All operands pre-rounded tf32 by producers.
// RND: 0 none, 1 round output, 2 store D full + D2 rounded.
template<int BN, int BMODE, int KK, int KALIGN, int AASY, int BASY,
         int BIASM, int ACT, int SMODE, int RND, int SPLITK>
__global__ void __launch_bounds__(256, 2)
gemm_k(GemmP p) {
    constexpr int BM = 128;
    constexpr int BK = (BN == 64) ? 32 : 16;
    constexpr int LDA_S = BK + 4, LDB_S = BN + 8;
    constexpr int WR = 4, WC = 2;
    constexpr int WN = BN/WC, NF = WN/8;
    constexpr int AG = BK/8;
    constexpr int ROWSTEP = 1024/BK;
    constexpr int KROWS = 256/BN;
    constexpr int BELEM = BK/KROWS;
    constexpr int ASZ = BM*LDA_S, BSZ = BK*LDB_S;
    constexpr bool RING = (AASY && BASY);
    constexpr int STG = RING ? 3 : 2;
    extern __shared__ float dyn[];
    float* As = dyn;
    float* Bs = dyn + STG*ASZ;

    const int tid = threadIdx.x, lane = tid & 31, warp = tid >> 5;
    const int wr = warp % WR, wc = warp / WR;
    const int m0 = blockIdx.y * BM, n0 = blockIdx.x * BN;

    int kbeg = 0, kend = p.K;
    if (SPLITK > 1) {
        int kc = ((p.K + SPLITK*BK - 1) / (SPLITK*BK)) * BK;
        kbeg = blockIdx.z * kc;
        kend = min(kbeg + kc, p.K);
    }

    // ---- staged A/B setup (used by non-async sides) ----
    const int ar_ = tid / (BK/4), ak4 = (tid & (BK/4 - 1)) * 4;
    const float* sarow[AG];
    int sastore[AG];
    #pragma unroll
    for (int g = 0; g < AG; g++) {
        sarow[g]   = p.A + (long long)(m0 + ar_ + ROWSTEP*g) * p.lda;
        sastore[g] = (ar_ + ROWSTEP*g)*LDA_S + ak4;
    }
    const int bnn = tid & (BN - 1);
    const int bkof = tid / BN;
    const float* sbb = p.Bp;
    bool snv = false;
    {
        int gn = n0 + bnn;
        snv = gn < p.N;
        int g = snv ? gn : 0;
        int b = 0, q = g;
        if (!(BMODE == 0 && p.sBb == 0)) { b = g / p.npos; q = g - b*p.npos; }
        sbb = p.Bp + b*p.sBb + q;
    }
    const int c_ = lane & 3, r_ = lane >> 2;
    const int arow_c = wr*32 + r_;

    float acc[2][NF][4];
    #pragma unroll
    for (int mi = 0; mi < 2; mi++)
        #pragma unroll
        for (int ni = 0; ni < NF; ni++)
            #pragma unroll
            for (int e = 0; e < 4; e++) acc[mi][ni][e] = 0.f;

#define COMPUTE_SLAB(Ac, Bc)                                                   \
    do {                                                                       \
        _Pragma("unroll")                                                      \
        for (int kc = 0; kc < BK/8; kc++) {                                    \
            uint32_t af[2][4];                                                 \
            _Pragma("unroll")                                                  \
            for (int mi = 0; mi < 2; mi++) {                                   \
                int rb_ = (arow_c + mi*16)*LDA_S + kc*8 + c_;                  \
                af[mi][0] = __float_as_uint((Ac)[rb_]);                        \
                af[mi][1] = __float_as_uint((Ac)[rb_ + 8*LDA_S]);              \
                af[mi][2] = __float_as_uint((Ac)[rb_ + 4]);                    \
                af[mi][3] = __float_as_uint((Ac)[rb_ + 8*LDA_S + 4]);          \
            }                                                                  \
            _Pragma("unroll")                                                  \
            for (int ni = 0; ni < NF; ni++) {                                  \
                int nn = wc*WN + ni*8 + r_;                                    \
                uint32_t bf[2];                                                \
                bf[0] = __float_as_uint((Bc)[(kc*8 + c_    )*LDB_S + nn]);     \
                bf[1] = __float_as_uint((Bc)[(kc*8 + c_ + 4)*LDB_S + nn]);     \
                mma_tf32(acc[0][ni], af[0], bf);                               \
                mma_tf32(acc[1][ni], af[1], bf);                               \
            }                                                                  \
        }                                                                      \
    } while (0)

    if (RING) {
        // ---------------- 3-stage cp.async ring ----------------
        const int nslab = (kend - kbeg + BK - 1) / BK;
        auto issue = [&](int s) {
            int kk = kbeg + s*BK;
            if (kk < kend) {
                float* An = As + (s % 3)*ASZ;
                float* Bn = Bs + (s % 3)*BSZ;
                #pragma unroll
                for (int g = 0; g < 2; g++) {
                    int id = tid + 256*g;
                    int row = id >> 2, cc4 = (id & 3) * 4;
                    cpa16(s2u32(&An[row*LDA_S + cc4]),
                          p.A + (long long)(m0 + row)*p.lda + kk + cc4);
                }
                #pragma unroll
                for (int g = 0; g < 2; g++) {
                    int id = tid + 256*g;
                    int k = id >> 5, cc4 = (id & 31) * 4;
                    int rem = p.N - (n0 + cc4);
                    int sb = rem >= 4 ? 16 : (rem > 0 ? rem*4 : 0);
                    const float* src = p.Bp + (long long)(kk + k)*p.ldb + (sb ? (n0 + cc4) : 0);
                    cpa16z(s2u32(&Bn[k*LDB_S + cc4]), src, sb);
                }
            }
            CP_COMMIT();
        };
        issue(0);
        issue(1);
        for (int s = 0; s < nslab; s++) {
            CP_WAIT1();
            __syncthreads();
            const float* Ac = As + (s % 3)*ASZ;
            const float* Bc = Bs + (s % 3)*BSZ;
            COMPUTE_SLAB(Ac, Bc);
            issue(s + 2);
        }
    } else {
        // ---------------- double-buffered path ----------------
        if (AASY) {
            #pragma unroll
            for (int g = 0; g < 2; g++) {
                int id = tid + 256*g;
                int row = id >> 2, cc4 = (id & 3) * 4;
                cpa16(s2u32(&As[row*LDA_S + cc4]),
                      p.A + (long long)(m0 + row)*p.lda + kbeg + cc4);
            }
        } else {
            #pragma unroll
            for (int g = 0; g < AG; g++) {
                float rv[4];
                #pragma unroll
                for (int j = 0; j < 4; j++) {
                    int gk = kbeg + ak4 + j;
                    rv[j] = (KALIGN || gk < p.K) ? sarow[g][gk] : 0.f;
                }
                *(float4*)&As[sastore[g]] = make_float4(rv[0], rv[1], rv[2], rv[3]);
            }
        }
        {
            #pragma unroll
            for (int r = 0; r < BELEM; r++) {
                int k = bkof + KROWS*r;
                float v = snv ? ldB<BMODE,KK>(p, sbb, kbeg + k) : 0.f;
                Bs[k*LDB_S + bnn] = v;
            }
        }
        if (AASY) { CP_COMMIT(); CP_WAIT0(); }
        __syncthreads();

        int buf = 0;
        for (int k0 = kbeg; k0 < kend; k0 += BK) {
            int kn = k0 + BK;
            bool more = kn < kend;
            float rsA[AG][4];
            float rsB[BELEM];
            if (more) {
                float* An = As + (buf^1)*ASZ;
                if (AASY) {
                    #pragma unroll
                    for (int g = 0; g < 2; g++) {
                        int id = tid + 256*g;
                        int row = id >> 2, cc4 = (id & 3) * 4;
                        cpa16(s2u32(&An[row*LDA_S + cc4]),
                              p.A + (long long)(m0 + row)*p.lda + kn + cc4);
                    }
                } else {
                    #pragma unroll
                    for (int g = 0; g < AG; g++)
                        #pragma unroll
                        for (int j = 0; j < 4; j++) {
                            int gk = kn + ak4 + j;
                            rsA[g][j] = (KALIGN || gk < p.K) ? sarow[g][gk] : 0.f;
                        }
                }
                #pragma unroll
                for (int r = 0; r < BELEM; r++)
                    rsB[r] = snv ? ldB<BMODE,KK>(p, sbb, kn + bkof + KROWS*r) : 0.f;
                if (AASY) CP_COMMIT();
            }
            const float* Ac = As + buf*ASZ;
            const float* Bc = Bs + buf*BSZ;
            COMPUTE_SLAB(Ac, Bc);
            if (more) {
                float* An = As + (buf^1)*ASZ;
                float* Bn = Bs + (buf^1)*BSZ;
                if (!AASY) {
                    #pragma unroll
                    for (int g = 0; g < AG; g++)
                        *(float4*)&An[sastore[g]] =
                            make_float4(rsA[g][0], rsA[g][1], rsA[g][2], rsA[g][3]);
                }
                #pragma unroll
                for (int r = 0; r < BELEM; r++)
                    Bn[(bkof + KROWS*r)*LDB_S + bnn] = rsB[r];
                if (AASY) CP_WAIT0();
            }
            __syncthreads();
            buf ^= 1;
        }
    }
#undef COMPUTE_SLAB

    // ---- epilogue ----
    if (SPLITK > 1) {
        float* pd = p.part + (size_t)blockIdx.z * ((size_t)p.M * p.N);
        #pragma unroll
        for (int mi = 0; mi < 2; mi++)
            #pragma unroll
            for (int half = 0; half < 2; half++) {
                int row = m0 + wr*32 + mi*16 + r_ + half*8;
                #pragma unroll
                for (int ni = 0; ni < NF; ni++)
                    #pragma unroll
                    for (int e = 0; e < 2; e++) {
                        int gn = n0 + wc*WN + ni*8 + c_*2 + e;
                        if (gn < p.N)
                            pd[(size_t)row*p.N + gn] = acc[mi][ni][half*2 + e];
                    }
            }
        return;
    }
    #pragma unroll
    for (int mi = 0; mi < 2; mi++) {
        #pragma unroll
        for (int half = 0; half < 2; half++) {
            int row = m0 + wr*32 + mi*16 + r_ + half*8;
            float brow = 0.f;
            if (BIASM == 1) brow = p.bias[row];
            else if (BIASM == 3) brow = p.bias[row / p.kt];
            int cout = 0, jj = 0;
            if (SMODE == 1) { cout = row / p.kt; jj = row - cout*p.kt; }
            #pragma unroll
            for (int ni = 0; ni < NF; ni++) {
                #pragma unroll
                for (int e = 0; e < 2; e++) {
                    int gn = n0 + wc*WN + ni*8 + c_*2 + e;
                    if (gn >= p.N) continue;
                    int b, q;
                    if (SMODE == 0 && p.sDb == 0) { b = 0; q = gn; }
                    else { b = gn / p.npos; q = gn - b*p.npos; }
                    float v = acc[mi][ni][half*2 + e] + brow;
                    if (BIASM == 2) v += p.bias[q];
                    if (ACT == 1) v = tanhf(v);
                    else if (ACT == 2) v = fmaxf(v, 0.f);
                    long long addr;
                    if (SMODE == 0) addr = b*p.sDb + (long long)row*p.ldd + q;
                    else addr = b*p.sDb + (long long)cout*p.mklen + (long long)q*p.kt + jj;
                    if (RND == 1) v = tfr(v);
                    p.D[addr] = v;
                    if (RND == 2) p.D2[addr] = tfr(v);
                }
            }
        }
    }
}

// ---------------- split-K reduce + bias + tanh (+optional round) ------------
__global__ void reduce_ep_k(const float* __restrict__ part, float* __restrict__ D,
                            const float* __restrict__ bias,
                            int S, int M, int N, long long sDb, int ldd, int npos, int rnd) {
    int idx = blockIdx.x*blockDim.x + threadIdx.x;
    if (idx >= M*N) return;
    int row = idx / N, gn = idx - row*N;
    size_t st = (size_t)M*N;
    float v = 0.f;
    for (int z = 0; z < S; z++) v += part[(size_t)z*st + idx];
    v = tanhf(v + bias[row]);
    if (rnd) v = tfr(v);
    int b = gn / npos, q = gn - b*npos;
    D[b*sDb + (long long)row*ldd + q] = v;
}

// ---------------- block reduce + layer norms ----------
__device__ __forceinline__ float blk_sum(float v) {
    __shared__ float sb[8];
    #pragma unroll
    for (int o = 16; o; o >>= 1) v += __shfl_xor_sync(0xffffffffu, v, o);
    if ((threadIdx.x & 31) == 0) sb[threadIdx.x >> 5] = v;
    __syncthreads();
    float t = 0.f;
    #pragma unroll
    for (int i = 0; i < 8; i++) t += sb[i];
    __syncthreads();
    return t;
}

__global__ void ln1_kernel(const float* __restrict__ xr, const float* __restrict__ x1,
                           const float* __restrict__ g, const float* __restrict__ bt,
                           float* __restrict__ out, int m) {
    int row = blockIdx.x;
    int b = row / m, t = row - b*m;
    int tid = threadIdx.x;
    size_t base = (size_t)b*NC*m + t;
    float v0 = xr[base + (size_t)tid*m]       + x1[base + (size_t)tid*m];
    float v1 = xr[base + (size_t)(tid+256)*m] + x1[base + (size_t)(tid+256)*m];
    float mu = blk_sum(v0 + v1) * (1.f/NC);
    float d0 = v0 - mu, d1 = v1 - mu;
    float var = blk_sum(d0*d0 + d1*d1) * (1.f/NC);
    float inv = rsqrtf(var + 1e-5f);
    out[base + (size_t)tid*m]       = tfr(d0*inv*g[tid]     + bt[tid]);
    out[base + (size_t)(tid+256)*m] = tfr(d1*inv*g[tid+256] + bt[tid+256]);
}

__global__ void branch_out_kernel(const float* __restrict__ y2, const float* __restrict__ resn,
                                  const float* __restrict__ g, const float* __restrict__ bt,
                                  float* __restrict__ br, int mk, int nbr) {
    int row = blockIdx.x;
    int b = row >> 10, l = row & 1023;
    int li = (l * mk) >> 10;
    int tid = threadIdx.x;
    size_t yb = (size_t)b*NC*mk + li;
    size_t rb = (size_t)b*NC*NL + l;
    float v0 = y2[yb + (size_t)tid*mk]       + resn[rb + (size_t)tid*NL];
    float v1 = y2[yb + (size_t)(tid+256)*mk] + resn[rb + (size_t)(tid+256)*NL];
    float mu = blk_sum(v0 + v1) * (1.f/NC);
    float d0 = v0 - mu, d1 = v1 - mu;
    float var = blk_sum(d0*d0 + d1*d1) * (1.f/NC);
    float inv = rsqrtf(var + 1e-5f);
    float* o = br + (size_t)row*(2*NC) + nbr*NC;
    o[tid]     = tfr(d0*inv*g[tid]     + bt[tid]);
    o[tid+256] = tfr(d1*inv*g[tid+256] + bt[tid+256]);
}

__global__ void final_ln_kernel(const float* __restrict__ mg, const float* __restrict__ h2,
                                const float* __restrict__ g, const float* __restrict__ bt,
                                float* __restrict__ out) {
    int row = blockIdx.x;
    int tid = threadIdx.x;
    size_t base = (size_t)row*NC;
    float v0 = mg[base + tid]       + h2[base + tid];
    float v1 = mg[base + tid + 256] + h2[base + tid + 256];
    float mu = blk_sum(v0 + v1) * (1.f/NC);
    float d0 = v0 - mu, d1 = v1 - mu;
    float var = blk_sum(d0*d0 + d1*d1) * (1.f/NC);
    float inv = rsqrtf(var + 1e-5f);
    out[base + tid]       = d0*inv*g[tid]     + bt[tid];
    out[base + tid + 256] = d1*inv*g[tid+256] + bt[tid+256];
}

template<int BN, int SPLITK>
static inline dim3 gg(int M, int N) { return dim3((N + BN - 1)/BN, M/128, SPLITK); }

template<int BN, int BMODE, int KK, int KALIGN, int AASY, int BASY,
         int BIASM, int ACT, int SMODE, int RND, int SPLITK = 1>
static void launch_gemm(const GemmP& p) {
    constexpr int BK = (BN == 64) ? 32 : 16;
    constexpr int STG = (AASY && BASY) ? 3 : 2;
    constexpr int SMEM = STG*(128*(BK + 4) + BK*(BN + 8))*4;
    cudaFuncSetAttribute((const void*)gemm_k<BN,BMODE,KK,KALIGN,AASY,BASY,BIASM,ACT,SMODE,RND,SPLITK>,
                         cudaFuncAttributeMaxDynamicSharedMemorySize, SMEM);
    gemm_k<BN,BMODE,KK,KALIGN,AASY,BASY,BIASM,ACT,SMODE,RND,SPLITK>
        <<<gg<BN,SPLITK>(p.M, p.N), 256, SMEM>>>(p);
}

extern "C" void kernel_launch(void* const* d_in, const int* in_sizes, int n_in,
                              void* d_out, int out_size) {
    (void)in_sizes; (void)n_in; (void)out_size;
    const float* src   = (const float*)d_in[0];
    const float* cw[2] = {(const float*)d_in[1],  (const float*)d_in[7]};
    const float* cb[2] = {(const float*)d_in[2],  (const float*)d_in[8]};
    const float* iw[2] = {(const float*)d_in[3],  (const float*)d_in[9]};
    const float* ib[2] = {(const float*)d_in[4],  (const float*)d_in[10]};
    const float* tw[2] = {(const float*)d_in[5],  (const float*)d_in[11]};
    const float* tb[2] = {(const float*)d_in[6],  (const float*)d_in[12]};
    const float* mw  = (const float*)d_in[13];
    const float* mb  = (const float*)d_in[14];
    const float* ng  = (const float*)d_in[15];
    const float* nb  = (const float*)d_in[16];
    const float* fw1 = (const float*)d_in[17];
    const float* fb1 = (const float*)d_in[18];
    const float* fw2 = (const float*)d_in[19];
    const float* fb2 = (const float*)d_in[20];
    const float* fng = (const float*)d_in[21];
    const float* fnb = (const float*)d_in[22];
    float* out = (float*)d_out;

    float *p_res,*p_cv,*p_x1,*p_x1t,*p_xf,*p_xi,*p_xr,*p_yln,*p_y2,*p_br,*p_mg,*p_mgt,*p_h1,*p_h2;
    float *p_W2a,*p_W2b,*p_Wm,*p_CM0,*p_CM20,*p_CM1,*p_CM21,*p_part,*p_im;
    float *p_cwT0,*p_cwT1,*p_iwT0,*p_iwT1,*p_f1T,*p_f2T;
    cudaGetSymbolAddress((void**)&p_res, g_res);
    cudaGetSymbolAddress((void**)&p_cv,  g_cv);
    cudaGetSymbolAddress((void**)&p_x1,  g_x1);
    cudaGetSymbolAddress((void**)&p_x1t, g_x1t);
    cudaGetSymbolAddress((void**)&p_xf,  g_xf);
    cudaGetSymbolAddress((void**)&p_xi,  g_xi);
    cudaGetSymbolAddress((void**)&p_xr,  g_xr);
    cudaGetSymbolAddress((void**)&p_yln, g_yln);
    cudaGetSymbolAddress((void**)&p_y2,  g_y2);
    cudaGetSymbolAddress((void**)&p_br,  g_br);
    cudaGetSymbolAddress((void**)&p_mg,  g_mg);
    cudaGetSymbolAddress((void**)&p_mgt, g_mgt);
    cudaGetSymbolAddress((void**)&p_h1,  g_h1);
    cudaGetSymbolAddress((void**)&p_h2,  g_h2);
    cudaGetSymbolAddress((void**)&p_W2a, g_W2a);
    cudaGetSymbolAddress((void**)&p_W2b, g_W2b);
    cudaGetSymbolAddress((void**)&p_Wm,  g_Wm);
    cudaGetSymbolAddress((void**)&p_CM0, g_CM0);
    cudaGetSymbolAddress((void**)&p_CM20,g_CM20);
    cudaGetSymbolAddress((void**)&p_CM1, g_CM1);
    cudaGetSymbolAddress((void**)&p_CM21,g_CM21);
    cudaGetSymbolAddress((void**)&p_part,g_part);
    cudaGetSymbolAddress((void**)&p_im,  g_im);
    cudaGetSymbolAddress((void**)&p_cwT0,g_cwT0);
    cudaGetSymbolAddress((void**)&p_cwT1,g_cwT1);
    cudaGetSymbolAddress((void**)&p_iwT0,g_iwT0);
    cudaGetSymbolAddress((void**)&p_iwT1,g_iwT1);
    cudaGetSymbolAddress((void**)&p_f1T, g_f1T);
    cudaGetSymbolAddress((void**)&p_f2T, g_f2T);

    const int Kk[2] = {12, 24}, NE[2] = {43, 22},
              MM[2] = {85, 43}, N2_[2] = {169, 85}, MKl[2] = {1020, 1032};
    float* CMv[2]  = {p_CM0, p_CM1};
    float* CM2v[2] = {p_CM20, p_CM21};
    float* W2v[2]  = {p_W2a, p_W2b};
    float* cwTv[2] = {p_cwT0, p_cwT1};
    float* iwTv[2] = {p_iwT0, p_iwT1};

    decomp_kernel<<<dim3(NL/32, NC/32, NB), dim3(32, 32)>>>(src, p_res);
    prep_all<<<4096, 256>>>(mw, p_Wm, tw[0], p_W2a, tw[1], p_W2b,
                            p_CM0, p_CM20, p_CM1, p_CM21,
                            cw[0], p_cwT0, cw[1], p_cwT1,
                            iw[0], p_iwT0, iw[1], p_iwT1,
                            fw1, p_f1T, fw2, p_f2T);

    // conv via materialized im2col + dense split-K GEMM (3-stage ring)
    for (int n = 0; n < 2; n++) {
        int k = Kk[n], ne2 = 2*NE[n];
        int Nn = NB*ne2;
        if (n == 0) im2col_conv_k<12,86><<<NC*12, 256>>>(p_res, p_im, 6);
        else        im2col_conv_k<24,44><<<NC*24, 256>>>(p_res + (size_t)NB*NC*NL, p_im, 12);
        GemmP p{};
        p.A = cwTv[n]; p.lda = NC*k;
        p.Bp = p_im; p.ldb = Nn; p.sBb = 0;
        p.part = p_part;
        p.bias = cb[n];
        p.M = NC; p.N = Nn; p.K = NC*k; p.npos = ne2;
        if (n == 0) launch_gemm<128,0,1,1,1,1,1,1,0,0,10>(p);
        else        launch_gemm<128,0,1,1,1,1,1,1,0,0,20>(p);
        reduce_ep_k<<<(NC*Nn + 255)/256, 256>>>(p_part, p_cv + (size_t)n*NB*NC*86, cb[n],
                                                (n == 0) ? 10 : 20, NC, Nn,
                                                (long long)NC*ne2, ne2, ne2, 0);
    }

    for (int n = 0; n < 2; n++) {
        int k = Kk[n], m = MM[n], N2 = N2_[n], mk = MKl[n];
        int ne2 = 2*NE[n];

        x1_kernel<<<1024, 256>>>(p_cv + (size_t)n*NB*NC*86, p_x1, p_x1t, m, ne2);
        { // real-DFT (ragged K, staged both; output rounded for iso B)
            GemmP p{};
            p.A = p_x1t; p.lda = m;
            p.Bp = CMv[n]; p.ldb = N2; p.sBb = 0;
            p.D = p_xf; p.sDb = 0; p.ldd = N2;
            p.M = NB*NC; p.N = N2; p.K = m; p.npos = N2;
            launch_gemm<64,0,1,0,0,0,0,0,0,1,1>(p);
        }
        { // isometric conv (valid), tanh — split-K, async A, staged B
            GemmP p{};
            p.A = iwTv[n]; p.lda = NC*m;
            p.Bp = p_xf; p.sBb = (long long)NC*N2; p.inner = N2;
            p.part = p_part;
            p.bias = ib[n];
            p.M = NC; p.N = NB*m; p.K = NC*m; p.npos = m;
            if (n == 0) launch_gemm<128,2,85,1,1,0,1,1,0,0,10>(p);
            else        launch_gemm<128,2,43,1,1,0,1,1,0,0,20>(p);
            reduce_ep_k<<<(NC*NB*m + 255)/256, 256>>>(p_part, p_xi, ib[n],
                                                      (n == 0) ? 10 : 20, NC, NB*m,
                                                      (long long)NC*m, m, m, 1);
        }
        { // real-IDFT (ragged K, staged both; xr full for residual)
            GemmP p{};
            p.A = p_xi; p.lda = m;
            p.Bp = CM2v[n]; p.ldb = m; p.sBb = 0;
            p.D = p_xr; p.sDb = 0; p.ldd = m;
            p.M = NB*NC; p.N = m; p.K = m; p.npos = m;
            launch_gemm<64,0,1,0,0,0,0,0,0,0,1>(p);
        }
        ln1_kernel<<<NB*m, 256>>>(p_xr, p_x1, ng, nb, p_yln, m);
        { // conv-transpose, tanh, scatter store — async A, staged B
            GemmP p{};
            p.A = W2v[n]; p.lda = NC;
            p.Bp = p_yln; p.ldb = m; p.sBb = (long long)NC*m;
            p.D = p_y2; p.sDb = (long long)NC*mk; p.kt = k; p.mklen = mk;
            p.bias = tb[n];
            p.M = NC*k; p.N = NB*m; p.K = NC; p.npos = m;
            launch_gemm<128,0,1,1,1,0,3,1,1,0,1>(p);
        }
        branch_out_kernel<<<NB*NL, 256>>>(p_y2, p_res + (size_t)n*NB*NC*NL, ng, nb, p_br, mk, n);
    }
    { // merge — 3-stage ring; dual store (mg full + mgt rounded)
        GemmP p{};
        p.A = p_br; p.lda = 2*NC;
        p.Bp = p_Wm; p.ldb = NC; p.sBb = 0;
        p.D = p_mg; p.D2 = p_mgt; p.sDb = 0; p.ldd = NC;
        p.bias = mb;
        p.M = NB*NL; p.N = NC; p.K = 2*NC; p.npos = NC;
        launch_gemm<128,0,1,1,1,1,2,0,0,2,1>(p);
    }
    { // FFN layer 1 (relu) — 3-stage ring; h1 rounded
        GemmP p{};
        p.A = p_mgt; p.lda = NC;
        p.Bp = p_f1T; p.ldb = 4*NC; p.sBb = 0;
        p.D = p_h1; p.sDb = 0; p.ldd = 4*NC;
        p.bias = fb1;
        p.M = NB*NL; p.N = 4*NC; p.K = NC; p.npos = 4*NC;
        launch_gemm<128,0,1,1,1,1,2,2,0,1,1>(p);
    }
    { // FFN layer 2 — 3-stage ring
        GemmP p{};
        p.A = p_h1; p.lda = 4*NC;
        p.Bp = p_f2T; p.ldb = NC; p.sBb = 0;
        p.D = p_h2; p.sDb = 0; p.ldd = NC;
        p.bias = fb2;
        p.M = NB*NL; p.N = NC; p.K = 4*NC; p.npos = NC;
        launch_gemm<128,0,1,1,1,1,2,0,0,0,1>(p);
    }
    final_ln_kernel<<<NB*NL, 256>>>(p_mg, p_h2, fng, fnb, out);
}

// round 17
// speedup vs baseline: 1.1633x; 1.1099x over previous
#include <cuda_runtime.h>
#include <math.h>
#include <stdint.h>

#define NB 32
#define NL 1024
#define NC 512
#define LH 512   // L/2

// ---------------- scratch (device globals; no allocations) ----------------
__device__ float g_res[(size_t)2*NB*NC*NL];
__device__ float g_cv [(size_t)2*NB*NC*86];
__device__ float g_x1 [(size_t)NB*NC*85];
__device__ float g_x1t[(size_t)NB*NC*85];
__device__ float g_xf [(size_t)NB*NC*169];
__device__ float g_xi [(size_t)NB*NC*85];
__device__ float g_xr [(size_t)NB*NC*85];
__device__ float g_yln[(size_t)NB*NC*85];
__device__ float g_y2 [(size_t)NB*NC*1032];
__device__ float g_br [(size_t)NB*NL*2*NC];
__device__ float g_mg [(size_t)NB*NL*NC];
__device__ float g_mgt[(size_t)NB*NL*NC];
__device__ float g_h1 [(size_t)NB*NL*4*NC];
__device__ float g_h2 [(size_t)NB*NL*NC];
__device__ float g_W2a[(size_t)NC*12*NC];
__device__ float g_W2b[(size_t)NC*24*NC];
__device__ float g_Wm [(size_t)2*NC*NC];
__device__ float g_CM0 [85*169];
__device__ float g_CM20[85*85];
__device__ float g_CM1 [43*85];
__device__ float g_CM21[43*43];
__device__ float g_cwT0[(size_t)NC*NC*12];
__device__ float g_cwT1[(size_t)NC*NC*24];
__device__ float g_iwT0[(size_t)NC*NC*85];
__device__ float g_iwT1[(size_t)NC*NC*43];
__device__ float g_f1T [(size_t)NC*4*NC];
__device__ float g_f2T [(size_t)NC*4*NC];
__device__ float g_part[(size_t)16*1024*1024];
__device__ float g_im [(size_t)18*1024*1024];

__device__ __forceinline__ uint32_t f2tf32(float v) {
    uint32_t u;
    asm("cvt.rna.tf32.f32 %0, %1;" : "=r"(u) : "f"(v));
    return u;
}
__device__ __forceinline__ float tfr(float v) { return __uint_as_float(f2tf32(v)); }

__device__ __forceinline__ uint32_t s2u32(const void* p) {
    return (uint32_t)__cvta_generic_to_shared(p);
}
__device__ __forceinline__ void cpa16(uint32_t dst, const void* src) {
    asm volatile("cp.async.cg.shared.global [%0], [%1], 16;" :: "r"(dst), "l"(src));
}
__device__ __forceinline__ void cpa16z(uint32_t dst, const void* src, int srcbytes) {
    asm volatile("cp.async.cg.shared.global [%0], [%1], 16, %2;"
                 :: "r"(dst), "l"(src), "r"(srcbytes));
}
__device__ __forceinline__ void cpa4z(uint32_t dst, const void* src, int srcbytes) {
    asm volatile("cp.async.ca.shared.global [%0], [%1], 4, %2;"
                 :: "r"(dst), "l"(src), "r"(srcbytes));
}
#define CP_COMMIT() asm volatile("cp.async.commit_group;" ::: "memory")
#define CP_WAIT0()  asm volatile("cp.async.wait_group 0;" ::: "memory")
#define CP_WAIT1()  asm volatile("cp.async.wait_group 1;" ::: "memory")

// ---------------- series decomp ----------------
__global__ void decomp_kernel(const float* __restrict__ src, float* __restrict__ res) {
    __shared__ float s[64][33];
    int b = blockIdx.z;
    int c0 = blockIdx.y * 32;
    int l0 = blockIdx.x * 32;
    int tx = threadIdx.x, ty = threadIdx.y;
    for (int r = ty; r < 64; r += 32) {
        int l = l0 - 16 + r;
        l = l < 0 ? 0 : (l > NL - 1 ? NL - 1 : l);
        s[r][tx] = src[((size_t)b*NL + l)*NC + c0 + tx];
    }
    __syncthreads();
    int base = tx + 16;
    float s17 = 0.f;
    #pragma unroll
    for (int j = -8; j <= 8; j++) s17 += s[base + j][ty];
    float s33 = s17;
    #pragma unroll
    for (int j = 9; j <= 16; j++) s33 += s[base - j][ty] + s[base + j][ty];
    float v = s[base][ty];
    size_t o = ((size_t)(b*NC + c0 + ty))*NL + l0 + tx;
    res[o] = v - s17 / 17.0f;
    res[(size_t)NB*NC*NL + o] = v - s33 / 33.0f;
}

// ---------------- fused prep ----------------
__global__ void prep_all(const float* __restrict__ mwt, float* __restrict__ Wm,
                         const float* __restrict__ tw0, float* __restrict__ W2a,
                         const float* __restrict__ tw1, float* __restrict__ W2b,
                         float* __restrict__ CM0, float* __restrict__ CM20,
                         float* __restrict__ CM1, float* __restrict__ CM21,
                         const float* __restrict__ cw0, float* __restrict__ cwT0,
                         const float* __restrict__ cw1, float* __restrict__ cwT1,
                         const float* __restrict__ iw0, float* __restrict__ iwT0,
                         const float* __restrict__ iw1, float* __restrict__ iwT1,
                         const float* __restrict__ f1, float* __restrict__ f1T,
                         const float* __restrict__ f2, float* __restrict__ f2T) {
    const double TWO_PI = 6.283185307179586476925286766559;
    const int tM = NC*NC*2, tA = NC*NC*12, tB = NC*NC*24;
    const int c0 = 85*169, c1 = 85*85, c2 = 43*85, c3 = 43*43;
    const int w0 = NC*NC*12, w1 = NC*NC*24, v0 = NC*NC*85, v1 = NC*NC*43;
    const int ff = NC*4*NC;
    long long total = (long long)tM + tA + tB + c0 + c1 + c2 + c3
                    + w0 + w1 + v0 + v1 + ff + ff;
    for (long long idx = (long long)blockIdx.x*blockDim.x + threadIdx.x; idx < total;
         idx += (long long)gridDim.x*blockDim.x) {
        long long i = idx;
        if (i < tM) {
            int o = (int)i / (NC*2);
            int rem = (int)i - o*NC*2;
            int c = rem >> 1, n = rem & 1;
            Wm[((size_t)n*NC + c)*NC + o] = tfr(mwt[i]);
            continue;
        }
        i -= tM;
        if (i < tA) {
            int cin = (int)i / (NC*12);
            int r   = (int)i - cin*(NC*12);
            W2a[(size_t)r*NC + cin] = tfr(tw0[i]);
            continue;
        }
        i -= tA;
        if (i < tB) {
            int cin = (int)i / (NC*24);
            int r   = (int)i - cin*(NC*24);
            W2b[(size_t)r*NC + cin] = tfr(tw1[i]);
            continue;
        }
        i -= tB;
        if (i < c0) {
            int t = (int)i / 169, f = (int)i - t*169;
            CM0[i] = tfr((float)cos(TWO_PI * (double)((long long)f*(t + 84)) / 169.0));
            continue;
        }
        i -= c0;
        if (i < c1) {
            int f = (int)i / 85, t = (int)i - f*85;
            CM20[i] = tfr((float)(cos(TWO_PI * (double)((long long)f*t) / 85.0) / 85.0));
            continue;
        }
        i -= c1;
        if (i < c2) {
            int t = (int)i / 85, f = (int)i - t*85;
            CM1[i] = tfr((float)cos(TWO_PI * (double)((long long)f*(t + 42)) / 85.0));
            continue;
        }
        i -= c2;
        if (i < c3) {
            int f = (int)i / 43, t = (int)i - f*43;
            CM21[i] = tfr((float)(cos(TWO_PI * (double)((long long)f*t) / 43.0) / 43.0));
            continue;
        }
        i -= c3;
        if (i < w0) { cwT0[i] = tfr(cw0[i]); continue; }
        i -= w0;
        if (i < w1) { cwT1[i] = tfr(cw1[i]); continue; }
        i -= w1;
        if (i < v0) { iwT0[i] = tfr(iw0[i]); continue; }
        i -= v0;
        if (i < v1) { iwT1[i] = tfr(iw1[i]); continue; }
        i -= v1;
        if (i < ff) { f1T[i] = tfr(f1[i]); continue; }
        i -= ff;
        f2T[i] = tfr(f2[i]);
    }
}

// ---------------- conv im2col materialization (tf32-rounded output) ---------
template<int KK, int NE2>
__global__ void im2col_conv_k(const float* __restrict__ res, float* __restrict__ out, int pad) {
    int gk = blockIdx.x;
    int cin = gk / KK, t = gk - cin*KK;
    const int N = NB*NE2;
    const float* rbase = res + (size_t)cin*NL;
    float* obase = out + (size_t)gk*N;
    int tb = t - pad;
    for (int gn = threadIdx.x; gn < N; gn += blockDim.x) {
        int b = gn / NE2, q = gn - b*NE2;
        int s = (q >> 1)*KK + tb;
        float v = (s >= 0 && s < LH) ? rbase[(size_t)b*NC*NL + 2*s + (q & 1)] : 0.f;
        obase[gn] = tfr(v);
    }
}

// ---------------- x1: exp-gated interleave (full + rounded copy) -----------
__global__ void x1_kernel(const float* __restrict__ cv, float* __restrict__ x1,
                          float* __restrict__ x1t, int m, int ne2) {
    size_t total = (size_t)NB*NC*m;
    for (size_t idx = (size_t)blockIdx.x*blockDim.x + threadIdx.x; idx < total;
         idx += (size_t)gridDim.x*blockDim.x) {
        int t = (int)(idx % m);
        size_t bc = idx / m;
        const float* c2 = cv + bc*ne2;
        float v = c2[t ^ 1] * expf(c2[t]);
        x1[idx] = v;
        x1t[idx] = tfr(v);
    }
}

// ---------------- GEMM params ----------------
struct GemmP {
    const float* A; int lda;
    const float* Bp; int ldb; long long sBb;
    float* D; long long sDb; int ldd;
    float* D2;
    const float* bias;
    int M, N, K;
    int npos;
    int pad, lhalf, inner;
    int kt, mklen;
    float* part;
};

__device__ __forceinline__ void mma_tf32(float c[4], const uint32_t a[4], const uint32_t b[2]) {
    asm("mma.sync.aligned.m16n8k8.row.col.f32.tf32.tf32.f32 "
        "{%0,%1,%2,%3},{%4,%5,%6,%7},{%8,%9},{%0,%1,%2,%3};"
        : "+f"(c[0]), "+f"(c[1]), "+f"(c[2]), "+f"(c[3])
        : "r"(a[0]), "r"(a[1]), "r"(a[2]), "r"(a[3]), "r"(b[0]), "r"(b[1]));
}

template<int BMODE, int KK>
__device__ __forceinline__ float ldB(const GemmP& p, const float* bbase, int gk) {
    if (gk >= p.K) return 0.f;
    if (BMODE == 0) return bbase[(long long)gk * p.ldb];
    int cin = gk / KK, t = gk - cin*KK;
    return bbase[(long long)cin*p.inner + t];
}
template<int BMODE, int KK>
__device__ __forceinline__ const float* ldB_addr(const GemmP& p, const float* bbase, int gk) {
    if (BMODE == 0) return bbase + (long long)gk * p.ldb;
    int cin = gk / KK, t = gk - cin*KK;
    return bbase + (long long)cin*p.inner + t;
}

// tf32 mma.sync GEMM, BM=128. BN=64: BK=32 staged; BN=128: BK=16.
// AASY && BASY>=1: 3-stage cp.async ring. BASY==1: 16B row copies (dense B).
// BASY==2: per-element 4B cp.async (im2col / batched B; requires K % BK == 0
// within each split-K chunk). All operands pre-rounded tf32 by producers.
// RND: 0 none, 1 round output, 2 store D full + D2 rounded.
template<int BN, int BMODE, int KK, int KALIGN, int AASY, int BASY,
         int BIASM, int ACT, int SMODE, int RND, int SPLITK>
__global__ void __launch_bounds__(256, 2)
gemm_k(GemmP p) {
    constexpr int BM = 128;
    constexpr int BK = (BN == 64) ? 32 : 16;
    constexpr int LDA_S = BK + 4, LDB_S = BN + 8;
    constexpr int WR = 4, WC = 2;
    constexpr int WN = BN/WC, NF = WN/8;
    constexpr int AG = BK/8;
    constexpr int ROWSTEP = 1024/BK;
    constexpr int KROWS = 256/BN;
    constexpr int BELEM = BK/KROWS;
    constexpr int ASZ = BM*LDA_S, BSZ = BK*LDB_S;
    constexpr bool RING = (AASY && BASY >= 1);
    constexpr int STG = RING ? 3 : 2;
    extern __shared__ float dyn[];
    float* As = dyn;
    float* Bs = dyn + STG*ASZ;

    const int tid = threadIdx.x, lane = tid & 31, warp = tid >> 5;
    const int wr = warp % WR, wc = warp / WR;
    const int m0 = blockIdx.y * BM, n0 = blockIdx.x * BN;

    int kbeg = 0, kend = p.K;
    if (SPLITK > 1) {
        int kc = ((p.K + SPLITK*BK - 1) / (SPLITK*BK)) * BK;
        kbeg = blockIdx.z * kc;
        kend = min(kbeg + kc, p.K);
    }

    // ---- staged A/B setup ----
    const int ar_ = tid / (BK/4), ak4 = (tid & (BK/4 - 1)) * 4;
    const float* sarow[AG];
    int sastore[AG];
    #pragma unroll
    for (int g = 0; g < AG; g++) {
        sarow[g]   = p.A + (long long)(m0 + ar_ + ROWSTEP*g) * p.lda;
        sastore[g] = (ar_ + ROWSTEP*g)*LDA_S + ak4;
    }
    const int bnn = tid & (BN - 1);
    const int bkof = tid / BN;
    const float* sbb = p.Bp;
    bool snv = false;
    {
        int gn = n0 + bnn;
        snv = gn < p.N;
        int g = snv ? gn : 0;
        int b = 0, q = g;
        if (!(BMODE == 0 && p.sBb == 0)) { b = g / p.npos; q = g - b*p.npos; }
        sbb = p.Bp + b*p.sBb + q;
    }
    const int c_ = lane & 3, r_ = lane >> 2;
    const int arow_c = wr*32 + r_;

    float acc[2][NF][4];
    #pragma unroll
    for (int mi = 0; mi < 2; mi++)
        #pragma unroll
        for (int ni = 0; ni < NF; ni++)
            #pragma unroll
            for (int e = 0; e < 4; e++) acc[mi][ni][e] = 0.f;

#define COMPUTE_SLAB(Ac, Bc)                                                   \
    do {                                                                       \
        _Pragma("unroll")                                                      \
        for (int kc = 0; kc < BK/8; kc++) {                                    \
            uint32_t af[2][4];                                                 \
            _Pragma("unroll")                                                  \
            for (int mi = 0; mi < 2; mi++) {                                   \
                int rb_ = (arow_c + mi*16)*LDA_S + kc*8 + c_;                  \
                af[mi][0] = __float_as_uint((Ac)[rb_]);                        \
                af[mi][1] = __float_as_uint((Ac)[rb_ + 8*LDA_S]);              \
                af[mi][2] = __float_as_uint((Ac)[rb_ + 4]);                    \
                af[mi][3] = __float_as_uint((Ac)[rb_ + 8*LDA_S + 4]);          \
            }                                                                  \
            _Pragma("unroll")                                                  \
            for (int ni = 0; ni < NF; ni++) {                                  \
                int nn = wc*WN + ni*8 + r_;                                    \
                uint32_t bf[2];                                                \
                bf[0] = __float_as_uint((Bc)[(kc*8 + c_    )*LDB_S + nn]);     \
                bf[1] = __float_as_uint((Bc)[(kc*8 + c_ + 4)*LDB_S + nn]);     \
                mma_tf32(acc[0][ni], af[0], bf);                               \
                mma_tf32(acc[1][ni], af[1], bf);                               \
            }                                                                  \
        }                                                                      \
    } while (0)

    if (RING) {
        // ---------------- 3-stage cp.async ring ----------------
        const int nslab = (kend - kbeg + BK - 1) / BK;
        auto issue = [&](int s) {
            int kk = kbeg + s*BK;
            if (kk < kend) {
                float* An = As + (s % 3)*ASZ;
                float* Bn = Bs + (s % 3)*BSZ;
                #pragma unroll
                for (int g = 0; g < 2; g++) {
                    int id = tid + 256*g;
                    int row = id >> 2, cc4 = (id & 3) * 4;
                    cpa16(s2u32(&An[row*LDA_S + cc4]),
                          p.A + (long long)(m0 + row)*p.lda + kk + cc4);
                }
                if (BASY == 1) {
                    #pragma unroll
                    for (int g = 0; g < 2; g++) {
                        int id = tid + 256*g;
                        int k = id >> 5, cc4 = (id & 31) * 4;
                        int rem = p.N - (n0 + cc4);
                        int sb = rem >= 4 ? 16 : (rem > 0 ? rem*4 : 0);
                        const float* src = p.Bp + (long long)(kk + k)*p.ldb + (sb ? (n0 + cc4) : 0);
                        cpa16z(s2u32(&Bn[k*LDB_S + cc4]), src, sb);
                    }
                } else {
                    #pragma unroll
                    for (int r = 0; r < BELEM; r++) {
                        int k = bkof + KROWS*r;
                        const float* src = ldB_addr<BMODE,KK>(p, sbb, kk + k);
                        cpa4z(s2u32(&Bn[k*LDB_S + bnn]), src, snv ? 4 : 0);
                    }
                }
            }
            CP_COMMIT();
        };
        issue(0);
        issue(1);
        for (int s = 0; s < nslab; s++) {
            CP_WAIT1();
            __syncthreads();
            const float* Ac = As + (s % 3)*ASZ;
            const float* Bc = Bs + (s % 3)*BSZ;
            COMPUTE_SLAB(Ac, Bc);
            issue(s + 2);
        }
    } else {
        // ---------------- double-buffered path ----------------
        if (AASY) {
            #pragma unroll
            for (int g = 0; g < 2; g++) {
                int id = tid + 256*g;
                int row = id >> 2, cc4 = (id & 3) * 4;
                cpa16(s2u32(&As[row*LDA_S + cc4]),
                      p.A + (long long)(m0 + row)*p.lda + kbeg + cc4);
            }
        } else {
            #pragma unroll
            for (int g = 0; g < AG; g++) {
                float rv[4];
                #pragma unroll
                for (int j = 0; j < 4; j++) {
                    int gk = kbeg + ak4 + j;
                    rv[j] = (KALIGN || gk < p.K) ? sarow[g][gk] : 0.f;
                }
                *(float4*)&As[sastore[g]] = make_float4(rv[0], rv[1], rv[2], rv[3]);
            }
        }
        {
            #pragma unroll
            for (int r = 0; r < BELEM; r++) {
                int k = bkof + KROWS*r;
                float v = snv ? ldB<BMODE,KK>(p, sbb, kbeg + k) : 0.f;
                Bs[k*LDB_S + bnn] = v;
            }
        }
        if (AASY) { CP_COMMIT(); CP_WAIT0(); }
        __syncthreads();

        int buf = 0;
        for (int k0 = kbeg; k0 < kend; k0 += BK) {
            int kn = k0 + BK;
            bool more = kn < kend;
            float rsA[AG][4];
            float rsB[BELEM];
            if (more) {
                float* An = As + (buf^1)*ASZ;
                if (AASY) {
                    #pragma unroll
                    for (int g = 0; g < 2; g++) {
                        int id = tid + 256*g;
                        int row = id >> 2, cc4 = (id & 3) * 4;
                        cpa16(s2u32(&An[row*LDA_S + cc4]),
                              p.A + (long long)(m0 + row)*p.lda + kn + cc4);
                    }
                } else {
                    #pragma unroll
                    for (int g = 0; g < AG; g++)
                        #pragma unroll
                        for (int j = 0; j < 4; j++) {
                            int gk = kn + ak4 + j;
                            rsA[g][j] = (KALIGN || gk < p.K) ? sarow[g][gk] : 0.f;
                        }
                }
                #pragma unroll
                for (int r = 0; r < BELEM; r++)
                    rsB[r] = snv ? ldB<BMODE,KK>(p, sbb, kn + bkof + KROWS*r) : 0.f;
                if (AASY) CP_COMMIT();
            }
            const float* Ac = As + buf*ASZ;
            const float* Bc = Bs + buf*BSZ;
            COMPUTE_SLAB(Ac, Bc);
            if (more) {
                float* An = As + (buf^1)*ASZ;
                float* Bn = Bs + (buf^1)*BSZ;
                if (!AASY) {
                    #pragma unroll
                    for (int g = 0; g < AG; g++)
                        *(float4*)&An[sastore[g]] =
                            make_float4(rsA[g][0], rsA[g][1], rsA[g][2], rsA[g][3]);
                }
                #pragma unroll
                for (int r = 0; r < BELEM; r++)
                    Bn[(bkof + KROWS*r)*LDB_S + bnn] = rsB[r];
                if (AASY) CP_WAIT0();
            }
            __syncthreads();
            buf ^= 1;
        }
    }
#undef COMPUTE_SLAB

    // ---- epilogue ----
    if (SPLITK > 1) {
        float* pd = p.part + (size_t)blockIdx.z * ((size_t)p.M * p.N);
        #pragma unroll
        for (int mi = 0; mi < 2; mi++)
            #pragma unroll
            for (int half = 0; half < 2; half++) {
                int row = m0 + wr*32 + mi*16 + r_ + half*8;
                #pragma unroll
                for (int ni = 0; ni < NF; ni++)
                    #pragma unroll
                    for (int e = 0; e < 2; e++) {
                        int gn = n0 + wc*WN + ni*8 + c_*2 + e;
                        if (gn < p.N)
                            pd[(size_t)row*p.N + gn] = acc[mi][ni][half*2 + e];
                    }
            }
        return;
    }
    #pragma unroll
    for (int mi = 0; mi < 2; mi++) {
        #pragma unroll
        for (int half = 0; half < 2; half++) {
            int row = m0 + wr*32 + mi*16 + r_ + half*8;
            float brow = 0.f;
            if (BIASM == 1) brow = p.bias[row];
            else if (BIASM == 3) brow = p.bias[row / p.kt];
            int cout = 0, jj = 0;
            if (SMODE == 1) { cout = row / p.kt; jj = row - cout*p.kt; }
            #pragma unroll
            for (int ni = 0; ni < NF; ni++) {
                #pragma unroll
                for (int e = 0; e < 2; e++) {
                    int gn = n0 + wc*WN + ni*8 + c_*2 + e;
                    if (gn >= p.N) continue;
                    int b, q;
                    if (SMODE == 0 && p.sDb == 0) { b = 0; q = gn; }
                    else { b = gn / p.npos; q = gn - b*p.npos; }
                    float v = acc[mi][ni][half*2 + e] + brow;
                    if (BIASM == 2) v += p.bias[q];
                    if (ACT == 1) v = tanhf(v);
                    else if (ACT == 2) v = fmaxf(v, 0.f);
                    long long addr;
                    if (SMODE == 0) addr = b*p.sDb + (long long)row*p.ldd + q;
                    else addr = b*p.sDb + (long long)cout*p.mklen + (long long)q*p.kt + jj;
                    if (RND == 1) v = tfr(v);
                    p.D[addr] = v;
                    if (RND == 2) p.D2[addr] = tfr(v);
                }
            }
        }
    }
}

// ---------------- split-K reduce + bias + tanh (+optional round) ------------
__global__ void reduce_ep_k(const float* __restrict__ part, float* __restrict__ D,
                            const float* __restrict__ bias,
                            int S, int M, int N, long long sDb, int ldd, int npos, int rnd) {
    int idx = blockIdx.x*blockDim.x + threadIdx.x;
    if (idx >= M*N) return;
    int row = idx / N, gn = idx - row*N;
    size_t st = (size_t)M*N;
    float v = 0.f;
    for (int z = 0; z < S; z++) v += part[(size_t)z*st + idx];
    v = tanhf(v + bias[row]);
    if (rnd) v = tfr(v);
    int b = gn / npos, q = gn - b*npos;
    D[b*sDb + (long long)row*ldd + q] = v;
}

// ---------------- block reduce + layer norms ----------
__device__ __forceinline__ float blk_sum(float v) {
    __shared__ float sb[8];
    #pragma unroll
    for (int o = 16; o; o >>= 1) v += __shfl_xor_sync(0xffffffffu, v, o);
    if ((threadIdx.x & 31) == 0) sb[threadIdx.x >> 5] = v;
    __syncthreads();
    float t = 0.f;
    #pragma unroll
    for (int i = 0; i < 8; i++) t += sb[i];
    __syncthreads();
    return t;
}

__global__ void ln1_kernel(const float* __restrict__ xr, const float* __restrict__ x1,
                           const float* __restrict__ g, const float* __restrict__ bt,
                           float* __restrict__ out, int m) {
    int row = blockIdx.x;
    int b = row / m, t = row - b*m;
    int tid = threadIdx.x;
    size_t base = (size_t)b*NC*m + t;
    float v0 = xr[base + (size_t)tid*m]       + x1[base + (size_t)tid*m];
    float v1 = xr[base + (size_t)(tid+256)*m] + x1[base + (size_t)(tid+256)*m];
    float mu = blk_sum(v0 + v1) * (1.f/NC);
    float d0 = v0 - mu, d1 = v1 - mu;
    float var = blk_sum(d0*d0 + d1*d1) * (1.f/NC);
    float inv = rsqrtf(var + 1e-5f);
    out[base + (size_t)tid*m]       = tfr(d0*inv*g[tid]     + bt[tid]);
    out[base + (size_t)(tid+256)*m] = tfr(d1*inv*g[tid+256] + bt[tid+256]);
}

// ---------------- branch_out: coalesced tiled LN (16 l x 512 c per block) ----
__global__ void branch_out_kernel(const float* __restrict__ y2, const float* __restrict__ resn,
                                  const float* __restrict__ g, const float* __restrict__ bt,
                                  float* __restrict__ br, int mk, int nbr) {
    __shared__ float sm[512*17];
    __shared__ float muA[16], invA[16];
    int b = blockIdx.y;
    int l0 = blockIdx.x * 16;
    int tid = threadIdx.x;
    const float* yb = y2   + (size_t)b*NC*mk;
    const float* rb = resn + (size_t)b*NC*NL;
    #pragma unroll
    for (int it = 0; it < 32; it++) {
        int e = it*256 + tid;
        int c = e >> 4, j = e & 15;
        int l = l0 + j;
        int li = (l * mk) >> 10;
        sm[c*17 + j] = yb[(size_t)c*mk + li] + rb[(size_t)c*NL + l];
    }
    __syncthreads();
    {
        int l = tid >> 4, s = tid & 15;
        float acc = 0.f;
        #pragma unroll
        for (int c = 0; c < 512; c += 16) acc += sm[(c + s)*17 + l];
        #pragma unroll
        for (int o = 8; o; o >>= 1) acc += __shfl_xor_sync(0xffffffffu, acc, o);
        float mu = acc * (1.f/NC);
        float vacc = 0.f;
        #pragma unroll
        for (int c = 0; c < 512; c += 16) { float d = sm[(c + s)*17 + l] - mu; vacc += d*d; }
        #pragma unroll
        for (int o = 8; o; o >>= 1) vacc += __shfl_xor_sync(0xffffffffu, vacc, o);
        if (s == 0) { muA[l] = mu; invA[l] = rsqrtf(vacc*(1.f/NC) + 1e-5f); }
    }
    __syncthreads();
    float* ob = br + (((size_t)b << 10) + l0)*(2*NC) + nbr*NC;
    #pragma unroll
    for (int it = 0; it < 32; it++) {
        int e = it*256 + tid;
        int l = e >> 9, c = e & 511;
        float v = (sm[c*17 + l] - muA[l]) * invA[l] * g[c] + bt[c];
        ob[(size_t)l*(2*NC) + c] = tfr(v);
    }
}

__global__ void final_ln_kernel(const float* __restrict__ mg, const float* __restrict__ h2,
                                const float* __restrict__ g, const float* __restrict__ bt,
                                float* __restrict__ out) {
    int row = blockIdx.x;
    int tid = threadIdx.x;
    size_t base = (size_t)row*NC;
    float v0 = mg[base + tid]       + h2[base + tid];
    float v1 = mg[base + tid + 256] + h2[base + tid + 256];
    float mu = blk_sum(v0 + v1) * (1.f/NC);
    float d0 = v0 - mu, d1 = v1 - mu;
    float var = blk_sum(d0*d0 + d1*d1) * (1.f/NC);
    float inv = rsqrtf(var + 1e-5f);
    out[base + tid]       = d0*inv*g[tid]     + bt[tid];
    out[base + tid + 256] = d1*inv*g[tid+256] + bt[tid+256];
}

template<int BN, int SPLITK>
static inline dim3 gg(int M, int N) { return dim3((N + BN - 1)/BN, M/128, SPLITK); }

template<int BN, int BMODE, int KK, int KALIGN, int AASY, int BASY,
         int BIASM, int ACT, int SMODE, int RND, int SPLITK = 1>
static void launch_gemm(const GemmP& p) {
    constexpr int BK = (BN == 64) ? 32 : 16;
    constexpr int STG = (AASY && BASY >= 1) ? 3 : 2;
    constexpr int SMEM = STG*(128*(BK + 4) + BK*(BN + 8))*4;
    cudaFuncSetAttribute((const void*)gemm_k<BN,BMODE,KK,KALIGN,AASY,BASY,BIASM,ACT,SMODE,RND,SPLITK>,
                         cudaFuncAttributeMaxDynamicSharedMemorySize, SMEM);
    gemm_k<BN,BMODE,KK,KALIGN,AASY,BASY,BIASM,ACT,SMODE,RND,SPLITK>
        <<<gg<BN,SPLITK>(p.M, p.N), 256, SMEM>>>(p);
}

extern "C" void kernel_launch(void* const* d_in, const int* in_sizes, int n_in,
                              void* d_out, int out_size) {
    (void)in_sizes; (void)n_in; (void)out_size;
    const float* src   = (const float*)d_in[0];
    const float* cw[2] = {(const float*)d_in[1],  (const float*)d_in[7]};
    const float* cb[2] = {(const float*)d_in[2],  (const float*)d_in[8]};
    const float* iw[2] = {(const float*)d_in[3],  (const float*)d_in[9]};
    const float* ib[2] = {(const float*)d_in[4],  (const float*)d_in[10]};
    const float* tw[2] = {(const float*)d_in[5],  (const float*)d_in[11]};
    const float* tb[2] = {(const float*)d_in[6],  (const float*)d_in[12]};
    const float* mw  = (const float*)d_in[13];
    const float* mb  = (const float*)d_in[14];
    const float* ng  = (const float*)d_in[15];
    const float* nb  = (const float*)d_in[16];
    const float* fw1 = (const float*)d_in[17];
    const float* fb1 = (const float*)d_in[18];
    const float* fw2 = (const float*)d_in[19];
    const float* fb2 = (const float*)d_in[20];
    const float* fng = (const float*)d_in[21];
    const float* fnb = (const float*)d_in[22];
    float* out = (float*)d_out;

    float *p_res,*p_cv,*p_x1,*p_x1t,*p_xf,*p_xi,*p_xr,*p_yln,*p_y2,*p_br,*p_mg,*p_mgt,*p_h1,*p_h2;
    float *p_W2a,*p_W2b,*p_Wm,*p_CM0,*p_CM20,*p_CM1,*p_CM21,*p_part,*p_im;
    float *p_cwT0,*p_cwT1,*p_iwT0,*p_iwT1,*p_f1T,*p_f2T;
    cudaGetSymbolAddress((void**)&p_res, g_res);
    cudaGetSymbolAddress((void**)&p_cv,  g_cv);
    cudaGetSymbolAddress((void**)&p_x1,  g_x1);
    cudaGetSymbolAddress((void**)&p_x1t, g_x1t);
    cudaGetSymbolAddress((void**)&p_xf,  g_xf);
    cudaGetSymbolAddress((void**)&p_xi,  g_xi);
    cudaGetSymbolAddress((void**)&p_xr,  g_xr);
    cudaGetSymbolAddress((void**)&p_yln, g_yln);
    cudaGetSymbolAddress((void**)&p_y2,  g_y2);
    cudaGetSymbolAddress((void**)&p_br,  g_br);
    cudaGetSymbolAddress((void**)&p_mg,  g_mg);
    cudaGetSymbolAddress((void**)&p_mgt, g_mgt);
    cudaGetSymbolAddress((void**)&p_h1,  g_h1);
    cudaGetSymbolAddress((void**)&p_h2,  g_h2);
    cudaGetSymbolAddress((void**)&p_W2a, g_W2a);
    cudaGetSymbolAddress((void**)&p_W2b, g_W2b);
    cudaGetSymbolAddress((void**)&p_Wm,  g_Wm);
    cudaGetSymbolAddress((void**)&p_CM0, g_CM0);
    cudaGetSymbolAddress((void**)&p_CM20,g_CM20);
    cudaGetSymbolAddress((void**)&p_CM1, g_CM1);
    cudaGetSymbolAddress((void**)&p_CM21,g_CM21);
    cudaGetSymbolAddress((void**)&p_part,g_part);
    cudaGetSymbolAddress((void**)&p_im,  g_im);
    cudaGetSymbolAddress((void**)&p_cwT0,g_cwT0);
    cudaGetSymbolAddress((void**)&p_cwT1,g_cwT1);
    cudaGetSymbolAddress((void**)&p_iwT0,g_iwT0);
    cudaGetSymbolAddress((void**)&p_iwT1,g_iwT1);
    cudaGetSymbolAddress((void**)&p_f1T, g_f1T);
    cudaGetSymbolAddress((void**)&p_f2T, g_f2T);

    const int Kk[2] = {12, 24}, NE[2] = {43, 22},
              MM[2] = {85, 43}, N2_[2] = {169, 85}, MKl[2] = {1020, 1032};
    float* CMv[2]  = {p_CM0, p_CM1};
    float* CM2v[2] = {p_CM20, p_CM21};
    float* W2v[2]  = {p_W2a, p_W2b};
    float* cwTv[2] = {p_cwT0, p_cwT1};
    float* iwTv[2] = {p_iwT0, p_iwT1};

    decomp_kernel<<<dim3(NL/32, NC/32, NB), dim3(32, 32)>>>(src, p_res);
    prep_all<<<4096, 256>>>(mw, p_Wm, tw[0], p_W2a, tw[1], p_W2b,
                            p_CM0, p_CM20, p_CM1, p_CM21,
                            cw[0], p_cwT0, cw[1], p_cwT1,
                            iw[0], p_iwT0, iw[1], p_iwT1,
                            fw1, p_f1T, fw2, p_f2T);

    // conv via materialized im2col + dense split-K GEMM (3-stage ring)
    for (int n = 0; n < 2; n++) {
        int k = Kk[n], ne2 = 2*NE[n];
        int Nn = NB*ne2;
        if (n == 0) im2col_conv_k<12,86><<<NC*12, 256>>>(p_res, p_im, 6);
        else        im2col_conv_k<24,44><<<NC*24, 256>>>(p_res + (size_t)NB*NC*NL, p_im, 12);
        GemmP p{};
        p.A = cwTv[n]; p.lda = NC*k;
        p.Bp = p_im; p.ldb = Nn; p.sBb = 0;
        p.part = p_part;
        p.bias = cb[n];
        p.M = NC; p.N = Nn; p.K = NC*k; p.npos = ne2;
        if (n == 0) launch_gemm<128,0,1,1,1,1,1,1,0,0,10>(p);
        else        launch_gemm<128,0,1,1,1,1,1,1,0,0,20>(p);
        reduce_ep_k<<<(NC*Nn + 255)/256, 256>>>(p_part, p_cv + (size_t)n*NB*NC*86, cb[n],
                                                (n == 0) ? 10 : 20, NC, Nn,
                                                (long long)NC*ne2, ne2, ne2, 0);
    }

    for (int n = 0; n < 2; n++) {
        int k = Kk[n], m = MM[n], N2 = N2_[n], mk = MKl[n];
        int ne2 = 2*NE[n];

        x1_kernel<<<1024, 256>>>(p_cv + (size_t)n*NB*NC*86, p_x1, p_x1t, m, ne2);
        { // real-DFT (ragged K, staged both; output rounded for iso B)
            GemmP p{};
            p.A = p_x1t; p.lda = m;
            p.Bp = CMv[n]; p.ldb = N2; p.sBb = 0;
            p.D = p_xf; p.sDb = 0; p.ldd = N2;
            p.M = NB*NC; p.N = N2; p.K = m; p.npos = N2;
            launch_gemm<64,0,1,0,0,0,0,0,0,1,1>(p);
        }
        { // isometric conv (valid), tanh — split-K, 3-stage ring (B via 4B cp.async)
            GemmP p{};
            p.A = iwTv[n]; p.lda = NC*m;
            p.Bp = p_xf; p.sBb = (long long)NC*N2; p.inner = N2;
            p.part = p_part;
            p.bias = ib[n];
            p.M = NC; p.N = NB*m; p.K = NC*m; p.npos = m;
            if (n == 0) launch_gemm<128,2,85,1,1,2,1,1,0,0,10>(p);
            else        launch_gemm<128,2,43,1,1,2,1,1,0,0,20>(p);
            reduce_ep_k<<<(NC*NB*m + 255)/256, 256>>>(p_part, p_xi, ib[n],
                                                      (n == 0) ? 10 : 20, NC, NB*m,
                                                      (long long)NC*m, m, m, 1);
        }
        { // real-IDFT (ragged K, staged both; xr full for residual)
            GemmP p{};
            p.A = p_xi; p.lda = m;
            p.Bp = CM2v[n]; p.ldb = m; p.sBb = 0;
            p.D = p_xr; p.sDb = 0; p.ldd = m;
            p.M = NB*NC; p.N = m; p.K = m; p.npos = m;
            launch_gemm<64,0,1,0,0,0,0,0,0,0,1>(p);
        }
        ln1_kernel<<<NB*m, 256>>>(p_xr, p_x1, ng, nb, p_yln, m);
        { // conv-transpose, tanh, scatter store — 3-stage ring (B via 4B cp.async)
            GemmP p{};
            p.A = W2v[n]; p.lda = NC;
            p.Bp = p_yln; p.ldb = m; p.sBb = (long long)NC*m;
            p.D = p_y2; p.sDb = (long long)NC*mk; p.kt = k; p.mklen = mk;
            p.bias = tb[n];
            p.M = NC*k; p.N = NB*m; p.K = NC; p.npos = m;
            launch_gemm<128,0,1,1,1,2,3,1,1,0,1>(p);
        }
        branch_out_kernel<<<dim3(NL/16, NB), 256>>>(p_y2, p_res + (size_t)n*NB*NC*NL,
                                                    ng, nb, p_br, mk, n);
    }
    { // merge — 3-stage ring; dual store (mg full + mgt rounded)
        GemmP p{};
        p.A = p_br; p.lda = 2*NC;
        p.Bp = p_Wm; p.ldb = NC; p.sBb = 0;
        p.D = p_mg; p.D2 = p_mgt; p.sDb = 0; p.ldd = NC;
        p.bias = mb;
        p.M = NB*NL; p.N = NC; p.K = 2*NC; p.npos = NC;
        launch_gemm<128,0,1,1,1,1,2,0,0,2,1>(p);
    }
    { // FFN layer 1 (relu) — 3-stage ring; h1 rounded
        GemmP p{};
        p.A = p_mgt; p.lda = NC;
        p.Bp = p_f1T; p.ldb = 4*NC; p.sBb = 0;
        p.D = p_h1; p.sDb = 0; p.ldd = 4*NC;
        p.bias = fb1;
        p.M = NB*NL; p.N = 4*NC; p.K = NC; p.npos = 4*NC;
        launch_gemm<128,0,1,1,1,1,2,2,0,1,1>(p);
    }
    { // FFN layer 2 — 3-stage ring
        GemmP p{};
        p.A = p_h1; p.lda = 4*NC;
        p.Bp = p_f2T; p.ldb = NC; p.sBb = 0;
        p.D = p_h2; p.sDb = 0; p.ldd = NC;
        p.bias = fb2;
        p.M = NB*NL; p.N = NC; p.K = 4*NC; p.npos = NC;
        launch_gemm<128,0,1,1,1,1,2,0,0,0,1>(p);
    }
    final_ln_kernel<<<NB*NL, 256>>>(p_mg, p_h2, fng, fnb, out);
}